// round 2
// baseline (speedup 1.0000x reference)
#include <cuda_runtime.h>
#include <cuda_bf16.h>
#include <math.h>

// Problem constants
#define T_TOK 2048
#define C_DIM 1024
#define F_DIM 4096
#define E_NUM 8
#define ROUTER_BLOCKS 256   // 8 tokens (warps) per block

// Scratch (allocation-free rule: __device__ globals)
__device__ int   g_cnt[E_NUM];
__device__ int   g_idx[E_NUM * T_TOK];
__device__ float g_prob[T_TOK];
__device__ float g_partial[ROUTER_BLOCKS * E_NUM];
__device__ float g_h[(size_t)T_TOK * F_DIM];   // 33.5 MB intermediate, keyed by token id

// ---------------------------------------------------------------------------
__global__ void init_kernel() {
    int i = threadIdx.x;
    if (i < E_NUM) g_cnt[i] = 0;
}

// ---------------------------------------------------------------------------
// Router: one warp per token. Deterministic importance partials per block.
__global__ void router_kernel(const float* __restrict__ x,
                              const float* __restrict__ rw,
                              const float* __restrict__ rb) {
    int warp = threadIdx.x >> 5;
    int lane = threadIdx.x & 31;
    int t = blockIdx.x * 8 + warp;

    float acc[E_NUM];
#pragma unroll
    for (int e = 0; e < E_NUM; e++) acc[e] = 0.f;

    const float* xr = x + (size_t)t * C_DIM;
    for (int c = lane; c < C_DIM; c += 32) {
        float xv = xr[c];
        const float4* r = (const float4*)(rw + c * E_NUM);
        float4 r0 = r[0];
        float4 r1 = r[1];
        acc[0] += xv * r0.x; acc[1] += xv * r0.y;
        acc[2] += xv * r0.z; acc[3] += xv * r0.w;
        acc[4] += xv * r1.x; acc[5] += xv * r1.y;
        acc[6] += xv * r1.z; acc[7] += xv * r1.w;
    }
#pragma unroll
    for (int e = 0; e < E_NUM; e++) {
#pragma unroll
        for (int o = 16; o > 0; o >>= 1)
            acc[e] += __shfl_xor_sync(0xffffffffu, acc[e], o);
    }

    __shared__ float s_p[8][E_NUM];
    if (lane == 0) {
        float lg[E_NUM];
        float mx = -1e30f; int am = 0;
#pragma unroll
        for (int e = 0; e < E_NUM; e++) {
            lg[e] = acc[e] + rb[e];
            if (lg[e] > mx) { mx = lg[e]; am = e; }
        }
        float s = 0.f, p[E_NUM];
#pragma unroll
        for (int e = 0; e < E_NUM; e++) { p[e] = expf(lg[e] - mx); s += p[e]; }
        float inv = 1.f / s;
#pragma unroll
        for (int e = 0; e < E_NUM; e++) { p[e] *= inv; s_p[warp][e] = p[e]; }
        g_prob[t] = p[am];
        int pos = atomicAdd(&g_cnt[am], 1);
        g_idx[am * T_TOK + pos] = t;
    }
    __syncthreads();
    if (threadIdx.x < E_NUM) {
        int e = threadIdx.x;
        float s = 0.f;
#pragma unroll
        for (int w = 0; w < 8; w++) s += s_p[w][e];
        g_partial[blockIdx.x * E_NUM + e] = s;
    }
}

// ---------------------------------------------------------------------------
// Aux loss: single thread, fixed summation order -> deterministic.
__global__ void aux_kernel(float* __restrict__ out, int out_size) {
    if (threadIdx.x != 0 || blockIdx.x != 0) return;
    float aux = 0.f;
    for (int e = 0; e < E_NUM; e++) {
        float imp = 0.f;
        for (int b = 0; b < ROUTER_BLOCKS; b++) imp += g_partial[b * E_NUM + e];
        imp *= (1.f / (float)T_TOK);
        float load = (float)g_cnt[e] * (1.f / (float)T_TOK);
        aux += imp * load;
    }
    out[out_size - 1] = (float)E_NUM * aux;
}

// ---------------------------------------------------------------------------
// Grouped SGEMM tiles: BM=64 (tokens, gathered), BN=64, BK=16, 256 threads,
// 4x4 micro-tile per thread.
#define BM 64
#define BN 64
#define BK 16
#define PAD 4

__global__ void ffn1_kernel(const float* __restrict__ x,
                            const float* __restrict__ w1,
                            const float* __restrict__ b1) {
    int e = blockIdx.y;
    int cnt = g_cnt[e];
    int m0 = blockIdx.z * BM;
    if (m0 >= cnt) return;
    int n0 = blockIdx.x * BN;

    __shared__ float As[BK][BM + PAD];
    __shared__ float Bs[BK][BN + PAD];
    __shared__ int   toks[BM];

    int tid = threadIdx.x;
    if (tid < BM) {
        int m = m0 + tid;
        toks[tid] = (m < cnt) ? g_idx[e * T_TOK + m] : -1;
    }
    __syncthreads();

    int tx = tid & 15, ty = tid >> 4;
    float acc[4][4];
#pragma unroll
    for (int i = 0; i < 4; i++)
#pragma unroll
        for (int j = 0; j < 4; j++) acc[i][j] = 0.f;

    const float* w1e = w1 + (size_t)e * C_DIM * F_DIM;
    int la_m = tid >> 2;         // 0..63
    int la_k = (tid & 3) * 4;    // 0,4,8,12
    int lb_k = tid >> 4;         // 0..15
    int lb_n = (tid & 15) * 4;   // 0..60
    int tkA = toks[la_m];
    const float* arow = (tkA >= 0) ? (x + (size_t)tkA * C_DIM) : x;

    for (int k0 = 0; k0 < C_DIM; k0 += BK) {
        float4 av = make_float4(0.f, 0.f, 0.f, 0.f);
        if (tkA >= 0) av = *(const float4*)(arow + k0 + la_k);
        As[la_k + 0][la_m] = av.x;
        As[la_k + 1][la_m] = av.y;
        As[la_k + 2][la_m] = av.z;
        As[la_k + 3][la_m] = av.w;
        float4 bv = *(const float4*)(w1e + (size_t)(k0 + lb_k) * F_DIM + n0 + lb_n);
        *(float4*)&Bs[lb_k][lb_n] = bv;
        __syncthreads();
#pragma unroll
        for (int kk = 0; kk < BK; kk++) {
            float a[4], b[4];
#pragma unroll
            for (int i = 0; i < 4; i++) a[i] = As[kk][ty * 4 + i];
#pragma unroll
            for (int j = 0; j < 4; j++) b[j] = Bs[kk][tx * 4 + j];
#pragma unroll
            for (int i = 0; i < 4; i++)
#pragma unroll
                for (int j = 0; j < 4; j++) acc[i][j] += a[i] * b[j];
        }
        __syncthreads();
    }

#pragma unroll
    for (int i = 0; i < 4; i++) {
        int tk = toks[ty * 4 + i];
        if (tk < 0) continue;
#pragma unroll
        for (int j = 0; j < 4; j++) {
            int n = n0 + tx * 4 + j;
            float v = acc[i][j] + b1[e * F_DIM + n];
            float sv = v / (1.f + expf(-v));    // silu
            g_h[(size_t)tk * F_DIM + n] = sv;
        }
    }
}

__global__ void ffn2_kernel(const float* __restrict__ w2,
                            const float* __restrict__ b2,
                            float* __restrict__ out) {
    int e = blockIdx.y;
    int cnt = g_cnt[e];
    int m0 = blockIdx.z * BM;
    if (m0 >= cnt) return;
    int n0 = blockIdx.x * BN;

    __shared__ float As[BK][BM + PAD];
    __shared__ float Bs[BK][BN + PAD];
    __shared__ int   toks[BM];

    int tid = threadIdx.x;
    if (tid < BM) {
        int m = m0 + tid;
        toks[tid] = (m < cnt) ? g_idx[e * T_TOK + m] : -1;
    }
    __syncthreads();

    int tx = tid & 15, ty = tid >> 4;
    float acc[4][4];
#pragma unroll
    for (int i = 0; i < 4; i++)
#pragma unroll
        for (int j = 0; j < 4; j++) acc[i][j] = 0.f;

    const float* w2e = w2 + (size_t)e * F_DIM * C_DIM;
    int la_m = tid >> 2;
    int la_k = (tid & 3) * 4;
    int lb_k = tid >> 4;
    int lb_n = (tid & 15) * 4;
    int tkA = toks[la_m];
    const float* arow = (tkA >= 0) ? (g_h + (size_t)tkA * F_DIM) : g_h;

    for (int k0 = 0; k0 < F_DIM; k0 += BK) {
        float4 av = make_float4(0.f, 0.f, 0.f, 0.f);
        if (tkA >= 0) av = *(const float4*)(arow + k0 + la_k);
        As[la_k + 0][la_m] = av.x;
        As[la_k + 1][la_m] = av.y;
        As[la_k + 2][la_m] = av.z;
        As[la_k + 3][la_m] = av.w;
        float4 bv = *(const float4*)(w2e + (size_t)(k0 + lb_k) * C_DIM + n0 + lb_n);
        *(float4*)&Bs[lb_k][lb_n] = bv;
        __syncthreads();
#pragma unroll
        for (int kk = 0; kk < BK; kk++) {
            float a[4], b[4];
#pragma unroll
            for (int i = 0; i < 4; i++) a[i] = As[kk][ty * 4 + i];
#pragma unroll
            for (int j = 0; j < 4; j++) b[j] = Bs[kk][tx * 4 + j];
#pragma unroll
            for (int i = 0; i < 4; i++)
#pragma unroll
                for (int j = 0; j < 4; j++) acc[i][j] += a[i] * b[j];
        }
        __syncthreads();
    }

#pragma unroll
    for (int i = 0; i < 4; i++) {
        int tk = toks[ty * 4 + i];
        if (tk < 0) continue;
        float p = g_prob[tk];
#pragma unroll
        for (int j = 0; j < 4; j++) {
            int n = n0 + tx * 4 + j;
            float v = (acc[i][j] + b2[e * C_DIM + n]) * p;
            out[(size_t)tk * C_DIM + n] = v;
        }
    }
}

// ---------------------------------------------------------------------------
extern "C" void kernel_launch(void* const* d_in, const int* in_sizes, int n_in,
                              void* d_out, int out_size) {
    const float* x  = (const float*)d_in[0];
    const float* rw = (const float*)d_in[1];
    const float* rb = (const float*)d_in[2];
    const float* w1 = (const float*)d_in[3];
    const float* b1 = (const float*)d_in[4];
    const float* w2 = (const float*)d_in[5];
    const float* b2 = (const float*)d_in[6];
    float* out = (float*)d_out;

    init_kernel<<<1, 32>>>();
    router_kernel<<<ROUTER_BLOCKS, 256>>>(x, rw, rb);
    aux_kernel<<<1, 32>>>(out, out_size);
    // GEMM1: [cnt_e,1024] x [1024,4096] -> silu -> g_h
    ffn1_kernel<<<dim3(F_DIM / BN, E_NUM, T_TOK / BM), 256>>>(x, w1, b1);
    // GEMM2: [cnt_e,4096] x [4096,1024] -> *prob -> out (scatter by token)
    ffn2_kernel<<<dim3(C_DIM / BN, E_NUM, T_TOK / BM), 256>>>(w2, b2, out);
}

// round 4
// speedup vs baseline: 2.0243x; 2.0243x over previous
#include <cuda_runtime.h>
#include <cuda_bf16.h>
#include <math.h>
#include <stdint.h>

// Problem constants
#define T_TOK 2048
#define C_DIM 1024
#define F_DIM 4096
#define E_NUM 8
#define ROUTER_BLOCKS 256   // 8 tokens (warps) per block

// Scratch (allocation-free rule: __device__ globals)
__device__ int   g_cnt[E_NUM];
__device__ int   g_idx[E_NUM * T_TOK];
__device__ float g_prob[T_TOK];
__device__ float g_partial[ROUTER_BLOCKS * E_NUM];
__device__ float g_h[(size_t)T_TOK * F_DIM];   // 33.5 MB intermediate, keyed by token id

// ---------------------------------------------------------------------------
__global__ void init_kernel() {
    int i = threadIdx.x;
    if (i < E_NUM) g_cnt[i] = 0;
}

// ---------------------------------------------------------------------------
// Router: one warp per token. Deterministic importance partials per block.
__global__ void router_kernel(const float* __restrict__ x,
                              const float* __restrict__ rw,
                              const float* __restrict__ rb) {
    int warp = threadIdx.x >> 5;
    int lane = threadIdx.x & 31;
    int t = blockIdx.x * 8 + warp;

    float acc[E_NUM];
#pragma unroll
    for (int e = 0; e < E_NUM; e++) acc[e] = 0.f;

    const float* xr = x + (size_t)t * C_DIM;
    for (int c = lane; c < C_DIM; c += 32) {
        float xv = xr[c];
        const float4* r = (const float4*)(rw + c * E_NUM);
        float4 r0 = r[0];
        float4 r1 = r[1];
        acc[0] += xv * r0.x; acc[1] += xv * r0.y;
        acc[2] += xv * r0.z; acc[3] += xv * r0.w;
        acc[4] += xv * r1.x; acc[5] += xv * r1.y;
        acc[6] += xv * r1.z; acc[7] += xv * r1.w;
    }
#pragma unroll
    for (int e = 0; e < E_NUM; e++) {
#pragma unroll
        for (int o = 16; o > 0; o >>= 1)
            acc[e] += __shfl_xor_sync(0xffffffffu, acc[e], o);
    }

    __shared__ float s_p[8][E_NUM];
    if (lane == 0) {
        float lg[E_NUM];
        float mx = -1e30f; int am = 0;
#pragma unroll
        for (int e = 0; e < E_NUM; e++) {
            lg[e] = acc[e] + rb[e];
            if (lg[e] > mx) { mx = lg[e]; am = e; }
        }
        float s = 0.f, p[E_NUM];
#pragma unroll
        for (int e = 0; e < E_NUM; e++) { p[e] = expf(lg[e] - mx); s += p[e]; }
        float inv = 1.f / s;
#pragma unroll
        for (int e = 0; e < E_NUM; e++) { p[e] *= inv; s_p[warp][e] = p[e]; }
        g_prob[t] = p[am];
        int pos = atomicAdd(&g_cnt[am], 1);
        g_idx[am * T_TOK + pos] = t;
    }
    __syncthreads();
    if (threadIdx.x < E_NUM) {
        int e = threadIdx.x;
        float s = 0.f;
#pragma unroll
        for (int w = 0; w < 8; w++) s += s_p[w][e];
        g_partial[blockIdx.x * E_NUM + e] = s;
    }
}

// ---------------------------------------------------------------------------
// Aux loss: parallel deterministic reduction (fixed lane mapping + fixed
// shfl tree + fixed final order -> bitwise deterministic across runs).
__global__ void aux_kernel(float* __restrict__ out, int out_size) {
    __shared__ float s_e[E_NUM];
    int wid = threadIdx.x >> 5;
    int lane = threadIdx.x & 31;
    if (wid < E_NUM) {
        float s = 0.f;
#pragma unroll
        for (int j = 0; j < ROUTER_BLOCKS / 32; j++)
            s += g_partial[(j * 32 + lane) * E_NUM + wid];
#pragma unroll
        for (int o = 16; o > 0; o >>= 1)
            s += __shfl_xor_sync(0xffffffffu, s, o);
        if (lane == 0) {
            float imp = s * (1.f / (float)T_TOK);
            float load = (float)g_cnt[wid] * (1.f / (float)T_TOK);
            s_e[wid] = imp * load;
        }
    }
    __syncthreads();
    if (threadIdx.x == 0) {
        float a = 0.f;
        for (int e = 0; e < E_NUM; e++) a += s_e[e];
        out[out_size - 1] = (float)E_NUM * a;
    }
}

// ===========================================================================
// bf16 split GEMM with warp-level mma.sync (HMMA) — valid on plain sm_100.
// ===========================================================================
#define LDSM4(r, a) \
    asm volatile("ldmatrix.sync.aligned.m8n8.x4.shared.b16 {%0,%1,%2,%3}, [%4];" \
        : "=r"((r)[0]), "=r"((r)[1]), "=r"((r)[2]), "=r"((r)[3]) : "r"(a))
#define LDSM4T(r, a) \
    asm volatile("ldmatrix.sync.aligned.m8n8.x4.trans.shared.b16 {%0,%1,%2,%3}, [%4];" \
        : "=r"((r)[0]), "=r"((r)[1]), "=r"((r)[2]), "=r"((r)[3]) : "r"(a))
#define MMA16816(d, a, b0, b1) \
    asm volatile("mma.sync.aligned.m16n8k16.row.col.f32.bf16.bf16.f32 " \
        "{%0,%1,%2,%3}, {%4,%5,%6,%7}, {%8,%9}, {%0,%1,%2,%3};" \
        : "+f"((d)[0]), "+f"((d)[1]), "+f"((d)[2]), "+f"((d)[3]) \
        : "r"((a)[0]), "r"((a)[1]), "r"((a)[2]), "r"((a)[3]), "r"(b0), "r"(b1))

__device__ __forceinline__ uint32_t sptr(const void* p) {
    return (uint32_t)__cvta_generic_to_shared(p);
}

// Convert float4 -> bf16 hi pair + lo pair (hi=truncate, lo=rn(residual)).
__device__ __forceinline__ void cvt_store(char* hip, char* lop, float4 f) {
    uint32_t h0, h1, l0, l1;
    asm("prmt.b32 %0, %1, %2, 0x7632;" : "=r"(h0)
        : "r"(__float_as_uint(f.x)), "r"(__float_as_uint(f.y)));
    asm("prmt.b32 %0, %1, %2, 0x7632;" : "=r"(h1)
        : "r"(__float_as_uint(f.z)), "r"(__float_as_uint(f.w)));
    float r0 = f.x - __uint_as_float(__float_as_uint(f.x) & 0xffff0000u);
    float r1 = f.y - __uint_as_float(__float_as_uint(f.y) & 0xffff0000u);
    float r2 = f.z - __uint_as_float(__float_as_uint(f.z) & 0xffff0000u);
    float r3 = f.w - __uint_as_float(__float_as_uint(f.w) & 0xffff0000u);
    asm("cvt.rn.bf16x2.f32 %0, %1, %2;" : "=r"(l0) : "f"(r1), "f"(r0));
    asm("cvt.rn.bf16x2.f32 %0, %1, %2;" : "=r"(l1) : "f"(r3), "f"(r2));
    *(uint2*)hip = make_uint2(h0, h1);
    *(uint2*)lop = make_uint2(l0, l1);
}

// Tile geometry
#define BM 128
#define BN 128
#define BKK 32
#define ASTR 40    // padded A row (bf16 elems)
#define BSTR 136   // padded B row (bf16 elems)

// FFN1: D = silu(x @ w1 + b1) -> g_h ; FFN2: D = (h @ w2 + b2)*prob -> out
template<int K_TOTAL, int A_STRIDE, int B_STRIDE, bool FFN1>
__global__ void __launch_bounds__(256, 1)
ffn_mma_kernel(const float* __restrict__ Asrc, const float* __restrict__ Bsrc,
               const float* __restrict__ bias, float* __restrict__ Dst) {
    const int e = blockIdx.y;
    const int cnt = g_cnt[e];
    const int m0 = blockIdx.z * BM;
    if (m0 >= cnt) return;
    const int n0 = blockIdx.x * BN;

    __shared__ int toks_s[BM];
    __shared__ __align__(16) uint16_t sAH[BM * ASTR];
    __shared__ __align__(16) uint16_t sAL[BM * ASTR];
    __shared__ __align__(16) uint16_t sBH[BKK * BSTR];
    __shared__ __align__(16) uint16_t sBL[BKK * BSTR];

    const int tid = threadIdx.x;
    const int wid = tid >> 5;
    const int lane = tid & 31;
    const int warp_m = wid >> 2;   // 0..1  (64 rows each)
    const int warp_n = wid & 3;    // 0..3  (32 cols each)

    if (tid < BM) {
        int m = m0 + tid;
        toks_s[tid] = (m < cnt) ? g_idx[e * T_TOK + m] : -1;
    }
    __syncthreads();

    // loader mapping: A: 2 threads/row (16 floats each); B: 8 threads/row
    const int a_row = tid >> 1;
    const int a_cg  = (tid & 1) * 16;
    const int tokA  = toks_s[a_row];
    const float* arow = (tokA >= 0) ? (Asrc + (size_t)tokA * A_STRIDE) : nullptr;
    const int b_row = tid >> 3;
    const int b_cg  = (tid & 7) * 16;
    const float* brow = Bsrc + (size_t)e * K_TOTAL * B_STRIDE
                       + (size_t)b_row * B_STRIDE + n0 + b_cg;

    float4 ra[4], rb[4];
    // prologue: LDG iter 0
#pragma unroll
    for (int j = 0; j < 4; j++) {
        ra[j] = arow ? *(const float4*)(arow + a_cg + j * 4)
                     : make_float4(0.f, 0.f, 0.f, 0.f);
        rb[j] = *(const float4*)(brow + j * 4);
    }

    float acc[4][4][4];
#pragma unroll
    for (int mi = 0; mi < 4; mi++)
#pragma unroll
        for (int nj = 0; nj < 4; nj++)
#pragma unroll
            for (int q = 0; q < 4; q++) acc[mi][nj][q] = 0.f;

    const uint32_t aH = sptr(sAH), aL = sptr(sAL);
    const uint32_t bH = sptr(sBH), bL = sptr(sBL);
    const int lm  = lane & 15;
    const int lg8 = (lane >> 4) * 8;
    const uint32_t aoff = (uint32_t)(((warp_m * 64 + lm) * ASTR + lg8) * 2);
    const uint32_t boff = (uint32_t)((lm * BSTR + warp_n * 32 + lg8) * 2);

    const int n_iters = K_TOTAL / BKK;
    for (int it = 0; it < n_iters; ++it) {
        // STS (convert fp32 -> bf16 hi/lo)
        {
            uint32_t ao = (uint32_t)((a_row * ASTR + a_cg) * 2);
            uint32_t bo = (uint32_t)((b_row * BSTR + b_cg) * 2);
#pragma unroll
            for (int j = 0; j < 4; j++) {
                cvt_store((char*)sAH + ao + j * 8, (char*)sAL + ao + j * 8, ra[j]);
                cvt_store((char*)sBH + bo + j * 8, (char*)sBL + bo + j * 8, rb[j]);
            }
        }
        __syncthreads();

        // prefetch next iter's gmem tile into registers
        if (it + 1 < n_iters) {
            const int k0 = (it + 1) * BKK;
#pragma unroll
            for (int j = 0; j < 4; j++) {
                ra[j] = arow ? *(const float4*)(arow + k0 + a_cg + j * 4)
                             : make_float4(0.f, 0.f, 0.f, 0.f);
                rb[j] = *(const float4*)(brow + (size_t)k0 * B_STRIDE + j * 4);
            }
        }

        // compute: 2 x k16 steps, 3-term bf16 split
#pragma unroll
        for (int kk = 0; kk < 2; kk++) {
            uint32_t fah[4][4], fal[4][4], fbh[2][4], fbl[2][4];
#pragma unroll
            for (int ni = 0; ni < 2; ni++) {
                uint32_t ba = boff + (uint32_t)((kk * 16 * BSTR + ni * 16) * 2);
                LDSM4T(fbh[ni], bH + ba);
                LDSM4T(fbl[ni], bL + ba);
            }
#pragma unroll
            for (int mi = 0; mi < 4; mi++) {
                uint32_t aa = aoff + (uint32_t)((mi * 16 * ASTR + kk * 16) * 2);
                LDSM4(fah[mi], aH + aa);
                LDSM4(fal[mi], aL + aa);
            }
#pragma unroll
            for (int mi = 0; mi < 4; mi++) {
#pragma unroll
                for (int nj = 0; nj < 4; nj++) {
                    uint32_t b0h = fbh[nj >> 1][(nj & 1) * 2];
                    uint32_t b1h = fbh[nj >> 1][(nj & 1) * 2 + 1];
                    uint32_t b0l = fbl[nj >> 1][(nj & 1) * 2];
                    uint32_t b1l = fbl[nj >> 1][(nj & 1) * 2 + 1];
                    MMA16816(acc[mi][nj], fah[mi], b0h, b1h);
                    MMA16816(acc[mi][nj], fah[mi], b0l, b1l);
                    MMA16816(acc[mi][nj], fal[mi], b0h, b1h);
                }
            }
        }
        __syncthreads();   // protect smem overwrite by next iter's STS
    }

    // epilogue: straight from registers
    const int r4 = lane >> 2;
    const int c2 = (lane & 3) * 2;
    const float* bias_p = bias + (size_t)e * B_STRIDE + n0 + warp_n * 32;
#pragma unroll
    for (int mi = 0; mi < 4; mi++) {
#pragma unroll
        for (int half = 0; half < 2; half++) {
            int rl = warp_m * 64 + mi * 16 + half * 8 + r4;
            int tok = toks_s[rl];
            if (tok < 0) continue;
            float p = 1.f;
            if (!FFN1) p = g_prob[tok];
            float* drow = Dst + (size_t)tok * B_STRIDE + n0 + warp_n * 32;
#pragma unroll
            for (int nj = 0; nj < 4; nj++) {
                int c = nj * 8 + c2;
                float v0 = acc[mi][nj][half * 2 + 0] + bias_p[c];
                float v1 = acc[mi][nj][half * 2 + 1] + bias_p[c + 1];
                float2 o;
                if (FFN1) {
                    o.x = v0 / (1.f + expf(-v0));
                    o.y = v1 / (1.f + expf(-v1));
                } else {
                    o.x = v0 * p;
                    o.y = v1 * p;
                }
                *(float2*)(drow + c) = o;
            }
        }
    }
}

// ---------------------------------------------------------------------------
extern "C" void kernel_launch(void* const* d_in, const int* in_sizes, int n_in,
                              void* d_out, int out_size) {
    const float* x  = (const float*)d_in[0];
    const float* rw = (const float*)d_in[1];
    const float* rb = (const float*)d_in[2];
    const float* w1 = (const float*)d_in[3];
    const float* b1 = (const float*)d_in[4];
    const float* w2 = (const float*)d_in[5];
    const float* b2 = (const float*)d_in[6];
    float* out = (float*)d_out;

    float* h = nullptr;
    cudaGetSymbolAddress((void**)&h, g_h);

    init_kernel<<<1, 32>>>();
    router_kernel<<<ROUTER_BLOCKS, 256>>>(x, rw, rb);
    aux_kernel<<<1, 256>>>(out, out_size);

    // FFN1: [cnt_e,1024] @ [1024,4096] -> silu -> g_h
    ffn_mma_kernel<C_DIM, C_DIM, F_DIM, true>
        <<<dim3(F_DIM / BN, E_NUM, T_TOK / BM), 256>>>(x, w1, b1, h);
    // FFN2: [cnt_e,4096] @ [4096,1024] -> *prob -> out
    ffn_mma_kernel<F_DIM, F_DIM, C_DIM, false>
        <<<dim3(C_DIM / BN, E_NUM, T_TOK / BM), 256>>>(h, w2, b2, out);
}

// round 5
// speedup vs baseline: 2.0873x; 1.0311x over previous
#include <cuda_runtime.h>
#include <cuda_bf16.h>
#include <math.h>
#include <stdint.h>

// Problem constants
#define T_TOK 2048
#define C_DIM 1024
#define F_DIM 4096
#define E_NUM 8
#define ROUTER_BLOCKS 256   // 8 tokens (warps) per block

// Scratch (allocation-free rule: __device__ globals)
__device__ int   g_cnt[E_NUM];
__device__ int   g_idx[E_NUM * T_TOK];
__device__ float g_prob[T_TOK];
__device__ float g_partial[ROUTER_BLOCKS * E_NUM];
__device__ float g_h[(size_t)T_TOK * F_DIM];   // 33.5 MB intermediate, keyed by token id

// ---------------------------------------------------------------------------
__global__ void init_kernel() {
    int i = threadIdx.x;
    if (i < E_NUM) g_cnt[i] = 0;
}

// ---------------------------------------------------------------------------
// Router: one warp per token. Deterministic importance partials per block.
__global__ void router_kernel(const float* __restrict__ x,
                              const float* __restrict__ rw,
                              const float* __restrict__ rb) {
    int warp = threadIdx.x >> 5;
    int lane = threadIdx.x & 31;
    int t = blockIdx.x * 8 + warp;

    float acc[E_NUM];
#pragma unroll
    for (int e = 0; e < E_NUM; e++) acc[e] = 0.f;

    const float* xr = x + (size_t)t * C_DIM;
    for (int c = lane; c < C_DIM; c += 32) {
        float xv = xr[c];
        const float4* r = (const float4*)(rw + c * E_NUM);
        float4 r0 = r[0];
        float4 r1 = r[1];
        acc[0] += xv * r0.x; acc[1] += xv * r0.y;
        acc[2] += xv * r0.z; acc[3] += xv * r0.w;
        acc[4] += xv * r1.x; acc[5] += xv * r1.y;
        acc[6] += xv * r1.z; acc[7] += xv * r1.w;
    }
#pragma unroll
    for (int e = 0; e < E_NUM; e++) {
#pragma unroll
        for (int o = 16; o > 0; o >>= 1)
            acc[e] += __shfl_xor_sync(0xffffffffu, acc[e], o);
    }

    __shared__ float s_p[8][E_NUM];
    if (lane == 0) {
        float lg[E_NUM];
        float mx = -1e30f; int am = 0;
#pragma unroll
        for (int e = 0; e < E_NUM; e++) {
            lg[e] = acc[e] + rb[e];
            if (lg[e] > mx) { mx = lg[e]; am = e; }
        }
        float s = 0.f, p[E_NUM];
#pragma unroll
        for (int e = 0; e < E_NUM; e++) { p[e] = expf(lg[e] - mx); s += p[e]; }
        float inv = 1.f / s;
#pragma unroll
        for (int e = 0; e < E_NUM; e++) { p[e] *= inv; s_p[warp][e] = p[e]; }
        g_prob[t] = p[am];
        int pos = atomicAdd(&g_cnt[am], 1);
        g_idx[am * T_TOK + pos] = t;
    }
    __syncthreads();
    if (threadIdx.x < E_NUM) {
        int e = threadIdx.x;
        float s = 0.f;
#pragma unroll
        for (int w = 0; w < 8; w++) s += s_p[w][e];
        g_partial[blockIdx.x * E_NUM + e] = s;
    }
}

// ---------------------------------------------------------------------------
// Aux loss: parallel deterministic reduction.
__global__ void aux_kernel(float* __restrict__ out, int out_size) {
    __shared__ float s_e[E_NUM];
    int wid = threadIdx.x >> 5;
    int lane = threadIdx.x & 31;
    if (wid < E_NUM) {
        float s = 0.f;
#pragma unroll
        for (int j = 0; j < ROUTER_BLOCKS / 32; j++)
            s += g_partial[(j * 32 + lane) * E_NUM + wid];
#pragma unroll
        for (int o = 16; o > 0; o >>= 1)
            s += __shfl_xor_sync(0xffffffffu, s, o);
        if (lane == 0) {
            float imp = s * (1.f / (float)T_TOK);
            float load = (float)g_cnt[wid] * (1.f / (float)T_TOK);
            s_e[wid] = imp * load;
        }
    }
    __syncthreads();
    if (threadIdx.x == 0) {
        float a = 0.f;
        for (int e = 0; e < E_NUM; e++) a += s_e[e];
        out[out_size - 1] = (float)E_NUM * a;
    }
}

// ===========================================================================
// bf16 split GEMM with warp-level mma.sync (HMMA) — valid on plain sm_100.
// Double-buffered SMEM, one barrier per K-iteration.
// ===========================================================================
#define LDSM4(r, a) \
    asm volatile("ldmatrix.sync.aligned.m8n8.x4.shared.b16 {%0,%1,%2,%3}, [%4];" \
        : "=r"((r)[0]), "=r"((r)[1]), "=r"((r)[2]), "=r"((r)[3]) : "r"(a))
#define LDSM4T(r, a) \
    asm volatile("ldmatrix.sync.aligned.m8n8.x4.trans.shared.b16 {%0,%1,%2,%3}, [%4];" \
        : "=r"((r)[0]), "=r"((r)[1]), "=r"((r)[2]), "=r"((r)[3]) : "r"(a))
#define MMA16816(d, a, b0, b1) \
    asm volatile("mma.sync.aligned.m16n8k16.row.col.f32.bf16.bf16.f32 " \
        "{%0,%1,%2,%3}, {%4,%5,%6,%7}, {%8,%9}, {%0,%1,%2,%3};" \
        : "+f"((d)[0]), "+f"((d)[1]), "+f"((d)[2]), "+f"((d)[3]) \
        : "r"((a)[0]), "r"((a)[1]), "r"((a)[2]), "r"((a)[3]), "r"(b0), "r"(b1))

__device__ __forceinline__ uint32_t sptr(const void* p) {
    return (uint32_t)__cvta_generic_to_shared(p);
}

// Convert float4 -> bf16 hi pair + lo pair (hi=truncate, lo=rn(residual)).
__device__ __forceinline__ void cvt_store(char* hip, char* lop, float4 f) {
    uint32_t h0, h1, l0, l1;
    asm("prmt.b32 %0, %1, %2, 0x7632;" : "=r"(h0)
        : "r"(__float_as_uint(f.x)), "r"(__float_as_uint(f.y)));
    asm("prmt.b32 %0, %1, %2, 0x7632;" : "=r"(h1)
        : "r"(__float_as_uint(f.z)), "r"(__float_as_uint(f.w)));
    float r0 = f.x - __uint_as_float(__float_as_uint(f.x) & 0xffff0000u);
    float r1 = f.y - __uint_as_float(__float_as_uint(f.y) & 0xffff0000u);
    float r2 = f.z - __uint_as_float(__float_as_uint(f.z) & 0xffff0000u);
    float r3 = f.w - __uint_as_float(__float_as_uint(f.w) & 0xffff0000u);
    asm("cvt.rn.bf16x2.f32 %0, %1, %2;" : "=r"(l0) : "f"(r1), "f"(r0));
    asm("cvt.rn.bf16x2.f32 %0, %1, %2;" : "=r"(l1) : "f"(r3), "f"(r2));
    *(uint2*)hip = make_uint2(h0, h1);
    *(uint2*)lop = make_uint2(l0, l1);
}

// Tile geometry
#define BM 128
#define BN 128
#define BKK 32
#define ASTR 40    // padded A row (bf16 elems)
#define BSTR 136   // padded B row (bf16 elems)

// Dynamic SMEM layout (one buffer; two buffers back-to-back)
#define ASZ   (BM * ASTR * 2)          // 10240 bytes per plane
#define BSZ   (BKK * BSTR * 2)         // 8704 bytes per plane
#define O_AH  0
#define O_AL  (O_AH + ASZ)
#define O_BH  (O_AL + ASZ)
#define O_BL  (O_BH + BSZ)
#define BUF_BYTES (2 * ASZ + 2 * BSZ)  // 37888
#define DYN_SMEM  (2 * BUF_BYTES)      // 75776

// FFN1: D = silu(x @ w1 + b1) -> g_h ; FFN2: D = (h @ w2 + b2)*prob -> out
template<int K_TOTAL, int A_STRIDE, int B_STRIDE, bool FFN1>
__global__ void __launch_bounds__(256, 1)
ffn_mma_kernel(const float* __restrict__ Asrc, const float* __restrict__ Bsrc,
               const float* __restrict__ bias, float* __restrict__ Dst) {
    const int e = blockIdx.y;
    const int cnt = g_cnt[e];
    const int m0 = blockIdx.z * BM;
    if (m0 >= cnt) return;
    const int n0 = blockIdx.x * BN;

    extern __shared__ __align__(16) char dsm[];
    __shared__ int toks_s[BM];

    const int tid = threadIdx.x;
    const int wid = tid >> 5;
    const int lane = tid & 31;
    const int warp_m = wid >> 2;   // 0..1  (64 rows each)
    const int warp_n = wid & 3;    // 0..3  (32 cols each)

    if (tid < BM) {
        int m = m0 + tid;
        toks_s[tid] = (m < cnt) ? g_idx[e * T_TOK + m] : -1;
    }
    __syncthreads();

    // loader mapping: A: 2 threads/row (16 floats each); B: 8 threads/row
    const int a_row = tid >> 1;
    const int a_cg  = (tid & 1) * 16;
    const int tokA  = toks_s[a_row];
    const float* arow = (tokA >= 0) ? (Asrc + (size_t)tokA * A_STRIDE) : nullptr;
    const int b_row = tid >> 3;
    const int b_cg  = (tid & 7) * 16;
    const float* brow = Bsrc + (size_t)e * K_TOTAL * B_STRIDE
                       + (size_t)b_row * B_STRIDE + n0 + b_cg;

    const uint32_t a_sts = (uint32_t)((a_row * ASTR + a_cg) * 2);
    const uint32_t b_sts = (uint32_t)((b_row * BSTR + b_cg) * 2);

    float4 ra[4], rb[4];
    // prologue: LDG iter 0
#pragma unroll
    for (int j = 0; j < 4; j++) {
        ra[j] = arow ? *(const float4*)(arow + a_cg + j * 4)
                     : make_float4(0.f, 0.f, 0.f, 0.f);
        rb[j] = *(const float4*)(brow + j * 4);
    }
    // STS iter 0 -> buffer 0
#pragma unroll
    for (int j = 0; j < 4; j++) {
        cvt_store(dsm + O_AH + a_sts + j * 8, dsm + O_AL + a_sts + j * 8, ra[j]);
        cvt_store(dsm + O_BH + b_sts + j * 8, dsm + O_BL + b_sts + j * 8, rb[j]);
    }
    // LDG iter 1
    {
        const int k0 = BKK;
#pragma unroll
        for (int j = 0; j < 4; j++) {
            ra[j] = arow ? *(const float4*)(arow + k0 + a_cg + j * 4)
                         : make_float4(0.f, 0.f, 0.f, 0.f);
            rb[j] = *(const float4*)(brow + (size_t)k0 * B_STRIDE + j * 4);
        }
    }
    __syncthreads();

    float acc[4][4][4];
#pragma unroll
    for (int mi = 0; mi < 4; mi++)
#pragma unroll
        for (int nj = 0; nj < 4; nj++)
#pragma unroll
            for (int q = 0; q < 4; q++) acc[mi][nj][q] = 0.f;

    const uint32_t dynb = sptr(dsm);
    const int lm  = lane & 15;
    const int lg8 = (lane >> 4) * 8;
    const uint32_t aoff = (uint32_t)(((warp_m * 64 + lm) * ASTR + lg8) * 2);
    const uint32_t boff = (uint32_t)((lm * BSTR + warp_n * 32 + lg8) * 2);

    const int n_iters = K_TOTAL / BKK;
    for (int it = 0; it < n_iters; ++it) {
        const int cur = it & 1;

        // STS iter it+1 into the other buffer (its readers finished last iter)
        if (it + 1 < n_iters) {
            char* nb = dsm + (cur ^ 1) * BUF_BYTES;
#pragma unroll
            for (int j = 0; j < 4; j++) {
                cvt_store(nb + O_AH + a_sts + j * 8, nb + O_AL + a_sts + j * 8, ra[j]);
                cvt_store(nb + O_BH + b_sts + j * 8, nb + O_BL + b_sts + j * 8, rb[j]);
            }
        }
        // LDG iter it+2 into registers
        if (it + 2 < n_iters) {
            const int k0 = (it + 2) * BKK;
#pragma unroll
            for (int j = 0; j < 4; j++) {
                ra[j] = arow ? *(const float4*)(arow + k0 + a_cg + j * 4)
                             : make_float4(0.f, 0.f, 0.f, 0.f);
                rb[j] = *(const float4*)(brow + (size_t)k0 * B_STRIDE + j * 4);
            }
        }

        // compute current buffer: 2 x k16 steps, 3-term bf16 split
        const uint32_t aH = dynb + cur * BUF_BYTES + O_AH;
        const uint32_t aL = dynb + cur * BUF_BYTES + O_AL;
        const uint32_t bH = dynb + cur * BUF_BYTES + O_BH;
        const uint32_t bL = dynb + cur * BUF_BYTES + O_BL;
#pragma unroll
        for (int kk = 0; kk < 2; kk++) {
            uint32_t fah[4][4], fal[4][4], fbh[2][4], fbl[2][4];
#pragma unroll
            for (int ni = 0; ni < 2; ni++) {
                uint32_t ba = boff + (uint32_t)((kk * 16 * BSTR + ni * 16) * 2);
                LDSM4T(fbh[ni], bH + ba);
                LDSM4T(fbl[ni], bL + ba);
            }
#pragma unroll
            for (int mi = 0; mi < 4; mi++) {
                uint32_t aa = aoff + (uint32_t)((mi * 16 * ASTR + kk * 16) * 2);
                LDSM4(fah[mi], aH + aa);
                LDSM4(fal[mi], aL + aa);
            }
#pragma unroll
            for (int mi = 0; mi < 4; mi++) {
#pragma unroll
                for (int nj = 0; nj < 4; nj++) {
                    uint32_t b0h = fbh[nj >> 1][(nj & 1) * 2];
                    uint32_t b1h = fbh[nj >> 1][(nj & 1) * 2 + 1];
                    uint32_t b0l = fbl[nj >> 1][(nj & 1) * 2];
                    uint32_t b1l = fbl[nj >> 1][(nj & 1) * 2 + 1];
                    MMA16816(acc[mi][nj], fah[mi], b0h, b1h);
                    MMA16816(acc[mi][nj], fah[mi], b0l, b1l);
                    MMA16816(acc[mi][nj], fal[mi], b0h, b1h);
                }
            }
        }
        __syncthreads();
    }

    // epilogue: straight from registers
    const int r4 = lane >> 2;
    const int c2 = (lane & 3) * 2;
    const float* bias_p = bias + (size_t)e * B_STRIDE + n0 + warp_n * 32;
#pragma unroll
    for (int mi = 0; mi < 4; mi++) {
#pragma unroll
        for (int half = 0; half < 2; half++) {
            int rl = warp_m * 64 + mi * 16 + half * 8 + r4;
            int tok = toks_s[rl];
            if (tok < 0) continue;
            float p = 1.f;
            if (!FFN1) p = g_prob[tok];
            float* drow = Dst + (size_t)tok * B_STRIDE + n0 + warp_n * 32;
#pragma unroll
            for (int nj = 0; nj < 4; nj++) {
                int c = nj * 8 + c2;
                float v0 = acc[mi][nj][half * 2 + 0] + bias_p[c];
                float v1 = acc[mi][nj][half * 2 + 1] + bias_p[c + 1];
                float2 o;
                if (FFN1) {
                    o.x = v0 / (1.f + expf(-v0));
                    o.y = v1 / (1.f + expf(-v1));
                } else {
                    o.x = v0 * p;
                    o.y = v1 * p;
                }
                *(float2*)(drow + c) = o;
            }
        }
    }
}

// ---------------------------------------------------------------------------
extern "C" void kernel_launch(void* const* d_in, const int* in_sizes, int n_in,
                              void* d_out, int out_size) {
    const float* x  = (const float*)d_in[0];
    const float* rw = (const float*)d_in[1];
    const float* rb = (const float*)d_in[2];
    const float* w1 = (const float*)d_in[3];
    const float* b1 = (const float*)d_in[4];
    const float* w2 = (const float*)d_in[5];
    const float* b2 = (const float*)d_in[6];
    float* out = (float*)d_out;

    cudaFuncSetAttribute(ffn_mma_kernel<C_DIM, C_DIM, F_DIM, true>,
                         cudaFuncAttributeMaxDynamicSharedMemorySize, DYN_SMEM);
    cudaFuncSetAttribute(ffn_mma_kernel<F_DIM, F_DIM, C_DIM, false>,
                         cudaFuncAttributeMaxDynamicSharedMemorySize, DYN_SMEM);

    float* h = nullptr;
    cudaGetSymbolAddress((void**)&h, g_h);

    init_kernel<<<1, 32>>>();
    router_kernel<<<ROUTER_BLOCKS, 256>>>(x, rw, rb);
    aux_kernel<<<1, 256>>>(out, out_size);

    // FFN1: [cnt_e,1024] @ [1024,4096] -> silu -> g_h
    ffn_mma_kernel<C_DIM, C_DIM, F_DIM, true>
        <<<dim3(F_DIM / BN, E_NUM, T_TOK / BM), 256, DYN_SMEM>>>(x, w1, b1, h);
    // FFN2: [cnt_e,4096] @ [4096,1024] -> *prob -> out
    ffn_mma_kernel<F_DIM, F_DIM, C_DIM, false>
        <<<dim3(C_DIM / BN, E_NUM, T_TOK / BM), 256, DYN_SMEM>>>(h, w2, b2, out);
}

// round 6
// speedup vs baseline: 2.0954x; 1.0039x over previous
#include <cuda_runtime.h>
#include <cuda_bf16.h>
#include <math.h>
#include <stdint.h>

// Problem constants
#define T_TOK 2048
#define C_DIM 1024
#define F_DIM 4096
#define E_NUM 8
#define ROUTER_BLOCKS 256   // 8 tokens (warps) per block

// Scratch (allocation-free rule: __device__ globals)
__device__ int   g_cnt[E_NUM];
__device__ int   g_idx[E_NUM * T_TOK];
__device__ float g_prob[T_TOK];
__device__ float g_partial[ROUTER_BLOCKS * E_NUM];
__device__ float g_h[(size_t)T_TOK * F_DIM];   // 33.5 MB intermediate, keyed by token id

// ---------------------------------------------------------------------------
__global__ void init_kernel() {
    int i = threadIdx.x;
    if (i < E_NUM) g_cnt[i] = 0;
}

// ---------------------------------------------------------------------------
// Router: one warp per token. Deterministic importance partials per block.
__global__ void router_kernel(const float* __restrict__ x,
                              const float* __restrict__ rw,
                              const float* __restrict__ rb) {
    int warp = threadIdx.x >> 5;
    int lane = threadIdx.x & 31;
    int t = blockIdx.x * 8 + warp;

    float acc[E_NUM];
#pragma unroll
    for (int e = 0; e < E_NUM; e++) acc[e] = 0.f;

    const float* xr = x + (size_t)t * C_DIM;
    for (int c = lane; c < C_DIM; c += 32) {
        float xv = xr[c];
        const float4* r = (const float4*)(rw + c * E_NUM);
        float4 r0 = r[0];
        float4 r1 = r[1];
        acc[0] += xv * r0.x; acc[1] += xv * r0.y;
        acc[2] += xv * r0.z; acc[3] += xv * r0.w;
        acc[4] += xv * r1.x; acc[5] += xv * r1.y;
        acc[6] += xv * r1.z; acc[7] += xv * r1.w;
    }
#pragma unroll
    for (int e = 0; e < E_NUM; e++) {
#pragma unroll
        for (int o = 16; o > 0; o >>= 1)
            acc[e] += __shfl_xor_sync(0xffffffffu, acc[e], o);
    }

    __shared__ float s_p[8][E_NUM];
    if (lane == 0) {
        float lg[E_NUM];
        float mx = -1e30f; int am = 0;
#pragma unroll
        for (int e = 0; e < E_NUM; e++) {
            lg[e] = acc[e] + rb[e];
            if (lg[e] > mx) { mx = lg[e]; am = e; }
        }
        float s = 0.f, p[E_NUM];
#pragma unroll
        for (int e = 0; e < E_NUM; e++) { p[e] = expf(lg[e] - mx); s += p[e]; }
        float inv = 1.f / s;
#pragma unroll
        for (int e = 0; e < E_NUM; e++) { p[e] *= inv; s_p[warp][e] = p[e]; }
        g_prob[t] = p[am];
        int pos = atomicAdd(&g_cnt[am], 1);
        g_idx[am * T_TOK + pos] = t;
    }
    __syncthreads();
    if (threadIdx.x < E_NUM) {
        int e = threadIdx.x;
        float s = 0.f;
#pragma unroll
        for (int w = 0; w < 8; w++) s += s_p[w][e];
        g_partial[blockIdx.x * E_NUM + e] = s;
    }
}

// ---------------------------------------------------------------------------
// Aux loss: parallel deterministic reduction.
__global__ void aux_kernel(float* __restrict__ out, int out_size) {
    __shared__ float s_e[E_NUM];
    int wid = threadIdx.x >> 5;
    int lane = threadIdx.x & 31;
    if (wid < E_NUM) {
        float s = 0.f;
#pragma unroll
        for (int j = 0; j < ROUTER_BLOCKS / 32; j++)
            s += g_partial[(j * 32 + lane) * E_NUM + wid];
#pragma unroll
        for (int o = 16; o > 0; o >>= 1)
            s += __shfl_xor_sync(0xffffffffu, s, o);
        if (lane == 0) {
            float imp = s * (1.f / (float)T_TOK);
            float load = (float)g_cnt[wid] * (1.f / (float)T_TOK);
            s_e[wid] = imp * load;
        }
    }
    __syncthreads();
    if (threadIdx.x == 0) {
        float a = 0.f;
        for (int e = 0; e < E_NUM; e++) a += s_e[e];
        out[out_size - 1] = (float)E_NUM * a;
    }
}

// ===========================================================================
// bf16 split GEMM with warp-level mma.sync (HMMA).
// 512 threads, 16 warps, warp tile 32x32, CTA tile 128x128x32,
// double-buffered SMEM, one barrier per K-iteration.
// ===========================================================================
#define LDSM4(r, a) \
    asm volatile("ldmatrix.sync.aligned.m8n8.x4.shared.b16 {%0,%1,%2,%3}, [%4];" \
        : "=r"((r)[0]), "=r"((r)[1]), "=r"((r)[2]), "=r"((r)[3]) : "r"(a))
#define LDSM4T(r, a) \
    asm volatile("ldmatrix.sync.aligned.m8n8.x4.trans.shared.b16 {%0,%1,%2,%3}, [%4];" \
        : "=r"((r)[0]), "=r"((r)[1]), "=r"((r)[2]), "=r"((r)[3]) : "r"(a))
#define MMA16816(d, a, b0, b1) \
    asm volatile("mma.sync.aligned.m16n8k16.row.col.f32.bf16.bf16.f32 " \
        "{%0,%1,%2,%3}, {%4,%5,%6,%7}, {%8,%9}, {%0,%1,%2,%3};" \
        : "+f"((d)[0]), "+f"((d)[1]), "+f"((d)[2]), "+f"((d)[3]) \
        : "r"((a)[0]), "r"((a)[1]), "r"((a)[2]), "r"((a)[3]), "r"(b0), "r"(b1))

__device__ __forceinline__ uint32_t sptr(const void* p) {
    return (uint32_t)__cvta_generic_to_shared(p);
}

// Convert float4 -> bf16 hi pair + lo pair (hi=truncate, lo=rn(residual)).
__device__ __forceinline__ void cvt_store(char* hip, char* lop, float4 f) {
    uint32_t h0, h1, l0, l1;
    asm("prmt.b32 %0, %1, %2, 0x7632;" : "=r"(h0)
        : "r"(__float_as_uint(f.x)), "r"(__float_as_uint(f.y)));
    asm("prmt.b32 %0, %1, %2, 0x7632;" : "=r"(h1)
        : "r"(__float_as_uint(f.z)), "r"(__float_as_uint(f.w)));
    float r0 = f.x - __uint_as_float(__float_as_uint(f.x) & 0xffff0000u);
    float r1 = f.y - __uint_as_float(__float_as_uint(f.y) & 0xffff0000u);
    float r2 = f.z - __uint_as_float(__float_as_uint(f.z) & 0xffff0000u);
    float r3 = f.w - __uint_as_float(__float_as_uint(f.w) & 0xffff0000u);
    asm("cvt.rn.bf16x2.f32 %0, %1, %2;" : "=r"(l0) : "f"(r1), "f"(r0));
    asm("cvt.rn.bf16x2.f32 %0, %1, %2;" : "=r"(l1) : "f"(r3), "f"(r2));
    *(uint2*)hip = make_uint2(h0, h1);
    *(uint2*)lop = make_uint2(l0, l1);
}

// Tile geometry
#define BM 128
#define BN 128
#define BKK 32
#define NTHREADS 512
#define ASTR 40    // padded A row (bf16 elems)
#define BSTR 136   // padded B row (bf16 elems)

// Dynamic SMEM layout (one buffer; two buffers back-to-back)
#define ASZ   (BM * ASTR * 2)          // 10240 bytes per plane
#define BSZ   (BKK * BSTR * 2)         // 8704 bytes per plane
#define O_AH  0
#define O_AL  (O_AH + ASZ)
#define O_BH  (O_AL + ASZ)
#define O_BL  (O_BH + BSZ)
#define BUF_BYTES (2 * ASZ + 2 * BSZ)  // 37888
#define DYN_SMEM  (2 * BUF_BYTES)      // 75776

// FFN1: D = silu(x @ w1 + b1) -> g_h ; FFN2: D = (h @ w2 + b2)*prob -> out
template<int K_TOTAL, int A_STRIDE, int B_STRIDE, bool FFN1>
__global__ void __launch_bounds__(NTHREADS, 1)
ffn_mma_kernel(const float* __restrict__ Asrc, const float* __restrict__ Bsrc,
               const float* __restrict__ bias, float* __restrict__ Dst) {
    const int e = blockIdx.y;
    const int cnt = g_cnt[e];
    const int m0 = blockIdx.z * BM;
    if (m0 >= cnt) return;
    const int n0 = blockIdx.x * BN;

    extern __shared__ __align__(16) char dsm[];
    __shared__ int toks_s[BM];

    const int tid = threadIdx.x;
    const int wid = tid >> 5;
    const int lane = tid & 31;
    const int warp_m = wid >> 2;   // 0..3  (32 rows each)
    const int warp_n = wid & 3;    // 0..3  (32 cols each)

    if (tid < BM) {
        int m = m0 + tid;
        toks_s[tid] = (m < cnt) ? g_idx[e * T_TOK + m] : -1;
    }
    __syncthreads();

    // loader mapping: A: 4 threads/row (8 floats each); B: 16 threads/row
    const int a_row = tid >> 2;
    const int a_cg  = (tid & 3) * 8;
    const int tokA  = toks_s[a_row];
    const float* arow = (tokA >= 0) ? (Asrc + (size_t)tokA * A_STRIDE) : nullptr;
    const int b_row = tid >> 4;
    const int b_cg  = (tid & 15) * 8;
    const float* brow = Bsrc + (size_t)e * K_TOTAL * B_STRIDE
                       + (size_t)b_row * B_STRIDE + n0 + b_cg;

    const uint32_t a_sts = (uint32_t)((a_row * ASTR + a_cg) * 2);
    const uint32_t b_sts = (uint32_t)((b_row * BSTR + b_cg) * 2);

    float4 ra[2], rb[2];
    // prologue: LDG iter 0
#pragma unroll
    for (int j = 0; j < 2; j++) {
        ra[j] = arow ? *(const float4*)(arow + a_cg + j * 4)
                     : make_float4(0.f, 0.f, 0.f, 0.f);
        rb[j] = *(const float4*)(brow + j * 4);
    }
    // STS iter 0 -> buffer 0
#pragma unroll
    for (int j = 0; j < 2; j++) {
        cvt_store(dsm + O_AH + a_sts + j * 8, dsm + O_AL + a_sts + j * 8, ra[j]);
        cvt_store(dsm + O_BH + b_sts + j * 8, dsm + O_BL + b_sts + j * 8, rb[j]);
    }
    // LDG iter 1
    {
        const int k0 = BKK;
#pragma unroll
        for (int j = 0; j < 2; j++) {
            ra[j] = arow ? *(const float4*)(arow + k0 + a_cg + j * 4)
                         : make_float4(0.f, 0.f, 0.f, 0.f);
            rb[j] = *(const float4*)(brow + (size_t)k0 * B_STRIDE + j * 4);
        }
    }
    __syncthreads();

    float acc[2][4][4];
#pragma unroll
    for (int mi = 0; mi < 2; mi++)
#pragma unroll
        for (int nj = 0; nj < 4; nj++)
#pragma unroll
            for (int q = 0; q < 4; q++) acc[mi][nj][q] = 0.f;

    const uint32_t dynb = sptr(dsm);
    const int lm  = lane & 15;
    const int lg8 = (lane >> 4) * 8;
    const uint32_t aoff = (uint32_t)(((warp_m * 32 + lm) * ASTR + lg8) * 2);
    const uint32_t boff = (uint32_t)((lm * BSTR + warp_n * 32 + lg8) * 2);

    const int n_iters = K_TOTAL / BKK;
    for (int it = 0; it < n_iters; ++it) {
        const int cur = it & 1;

        // STS iter it+1 into the other buffer (its readers finished last iter)
        if (it + 1 < n_iters) {
            char* nb = dsm + (cur ^ 1) * BUF_BYTES;
#pragma unroll
            for (int j = 0; j < 2; j++) {
                cvt_store(nb + O_AH + a_sts + j * 8, nb + O_AL + a_sts + j * 8, ra[j]);
                cvt_store(nb + O_BH + b_sts + j * 8, nb + O_BL + b_sts + j * 8, rb[j]);
            }
        }
        // LDG iter it+2 into registers
        if (it + 2 < n_iters) {
            const int k0 = (it + 2) * BKK;
#pragma unroll
            for (int j = 0; j < 2; j++) {
                ra[j] = arow ? *(const float4*)(arow + k0 + a_cg + j * 4)
                             : make_float4(0.f, 0.f, 0.f, 0.f);
                rb[j] = *(const float4*)(brow + (size_t)k0 * B_STRIDE + j * 4);
            }
        }

        // compute current buffer: 2 x k16 steps, 3-term bf16 split
        const uint32_t aH = dynb + cur * BUF_BYTES + O_AH;
        const uint32_t aL = dynb + cur * BUF_BYTES + O_AL;
        const uint32_t bH = dynb + cur * BUF_BYTES + O_BH;
        const uint32_t bL = dynb + cur * BUF_BYTES + O_BL;
#pragma unroll
        for (int kk = 0; kk < 2; kk++) {
            uint32_t fah[2][4], fal[2][4], fbh[2][4], fbl[2][4];
#pragma unroll
            for (int ni = 0; ni < 2; ni++) {
                uint32_t ba = boff + (uint32_t)((kk * 16 * BSTR + ni * 16) * 2);
                LDSM4T(fbh[ni], bH + ba);
                LDSM4T(fbl[ni], bL + ba);
            }
#pragma unroll
            for (int mi = 0; mi < 2; mi++) {
                uint32_t aa = aoff + (uint32_t)((mi * 16 * ASTR + kk * 16) * 2);
                LDSM4(fah[mi], aH + aa);
                LDSM4(fal[mi], aL + aa);
            }
#pragma unroll
            for (int mi = 0; mi < 2; mi++) {
#pragma unroll
                for (int nj = 0; nj < 4; nj++) {
                    uint32_t b0h = fbh[nj >> 1][(nj & 1) * 2];
                    uint32_t b1h = fbh[nj >> 1][(nj & 1) * 2 + 1];
                    uint32_t b0l = fbl[nj >> 1][(nj & 1) * 2];
                    uint32_t b1l = fbl[nj >> 1][(nj & 1) * 2 + 1];
                    MMA16816(acc[mi][nj], fah[mi], b0h, b1h);
                    MMA16816(acc[mi][nj], fah[mi], b0l, b1l);
                    MMA16816(acc[mi][nj], fal[mi], b0h, b1h);
                }
            }
        }
        __syncthreads();
    }

    // epilogue: straight from registers
    const int r4 = lane >> 2;
    const int c2 = (lane & 3) * 2;
    const float* bias_p = bias + (size_t)e * B_STRIDE + n0 + warp_n * 32;
#pragma unroll
    for (int mi = 0; mi < 2; mi++) {
#pragma unroll
        for (int half = 0; half < 2; half++) {
            int rl = warp_m * 32 + mi * 16 + half * 8 + r4;
            int tok = toks_s[rl];
            if (tok < 0) continue;
            float p = 1.f;
            if (!FFN1) p = g_prob[tok];
            float* drow = Dst + (size_t)tok * B_STRIDE + n0 + warp_n * 32;
#pragma unroll
            for (int nj = 0; nj < 4; nj++) {
                int c = nj * 8 + c2;
                float v0 = acc[mi][nj][half * 2 + 0] + bias_p[c];
                float v1 = acc[mi][nj][half * 2 + 1] + bias_p[c + 1];
                float2 o;
                if (FFN1) {
                    o.x = v0 / (1.f + expf(-v0));
                    o.y = v1 / (1.f + expf(-v1));
                } else {
                    o.x = v0 * p;
                    o.y = v1 * p;
                }
                *(float2*)(drow + c) = o;
            }
        }
    }
}

// ---------------------------------------------------------------------------
extern "C" void kernel_launch(void* const* d_in, const int* in_sizes, int n_in,
                              void* d_out, int out_size) {
    const float* x  = (const float*)d_in[0];
    const float* rw = (const float*)d_in[1];
    const float* rb = (const float*)d_in[2];
    const float* w1 = (const float*)d_in[3];
    const float* b1 = (const float*)d_in[4];
    const float* w2 = (const float*)d_in[5];
    const float* b2 = (const float*)d_in[6];
    float* out = (float*)d_out;

    cudaFuncSetAttribute(ffn_mma_kernel<C_DIM, C_DIM, F_DIM, true>,
                         cudaFuncAttributeMaxDynamicSharedMemorySize, DYN_SMEM);
    cudaFuncSetAttribute(ffn_mma_kernel<F_DIM, F_DIM, C_DIM, false>,
                         cudaFuncAttributeMaxDynamicSharedMemorySize, DYN_SMEM);

    float* h = nullptr;
    cudaGetSymbolAddress((void**)&h, g_h);

    init_kernel<<<1, 32>>>();
    router_kernel<<<ROUTER_BLOCKS, 256>>>(x, rw, rb);
    aux_kernel<<<1, 256>>>(out, out_size);

    // FFN1: [cnt_e,1024] @ [1024,4096] -> silu -> g_h
    ffn_mma_kernel<C_DIM, C_DIM, F_DIM, true>
        <<<dim3(F_DIM / BN, E_NUM, T_TOK / BM), NTHREADS, DYN_SMEM>>>(x, w1, b1, h);
    // FFN2: [cnt_e,4096] @ [4096,1024] -> *prob -> out
    ffn_mma_kernel<F_DIM, F_DIM, C_DIM, false>
        <<<dim3(C_DIM / BN, E_NUM, T_TOK / BM), NTHREADS, DYN_SMEM>>>(h, w2, b2, out);
}

// round 7
// speedup vs baseline: 2.1156x; 1.0097x over previous
#include <cuda_runtime.h>
#include <cuda_bf16.h>
#include <math.h>
#include <stdint.h>

// Problem constants
#define T_TOK 2048
#define C_DIM 1024
#define F_DIM 4096
#define E_NUM 8
#define ROUTER_BLOCKS 256   // 8 tokens (warps) per block

// Scratch (allocation-free rule: __device__ globals)
__device__ int   g_cnt[E_NUM];
__device__ int   g_idx[E_NUM * T_TOK];
__device__ float g_prob[T_TOK];
__device__ float g_partial[ROUTER_BLOCKS * E_NUM];
__device__ float g_h[(size_t)T_TOK * F_DIM];   // 33.5 MB intermediate, keyed by token id

// ---------------------------------------------------------------------------
__global__ void init_kernel() {
    int i = threadIdx.x;
    if (i < E_NUM) g_cnt[i] = 0;
}

// ---------------------------------------------------------------------------
// Router: one warp per token. Deterministic importance partials per block.
__global__ void router_kernel(const float* __restrict__ x,
                              const float* __restrict__ rw,
                              const float* __restrict__ rb) {
    int warp = threadIdx.x >> 5;
    int lane = threadIdx.x & 31;
    int t = blockIdx.x * 8 + warp;

    float acc[E_NUM];
#pragma unroll
    for (int e = 0; e < E_NUM; e++) acc[e] = 0.f;

    const float* xr = x + (size_t)t * C_DIM;
    for (int c = lane; c < C_DIM; c += 32) {
        float xv = xr[c];
        const float4* r = (const float4*)(rw + c * E_NUM);
        float4 r0 = r[0];
        float4 r1 = r[1];
        acc[0] += xv * r0.x; acc[1] += xv * r0.y;
        acc[2] += xv * r0.z; acc[3] += xv * r0.w;
        acc[4] += xv * r1.x; acc[5] += xv * r1.y;
        acc[6] += xv * r1.z; acc[7] += xv * r1.w;
    }
#pragma unroll
    for (int e = 0; e < E_NUM; e++) {
#pragma unroll
        for (int o = 16; o > 0; o >>= 1)
            acc[e] += __shfl_xor_sync(0xffffffffu, acc[e], o);
    }

    __shared__ float s_p[8][E_NUM];
    if (lane == 0) {
        float lg[E_NUM];
        float mx = -1e30f; int am = 0;
#pragma unroll
        for (int e = 0; e < E_NUM; e++) {
            lg[e] = acc[e] + rb[e];
            if (lg[e] > mx) { mx = lg[e]; am = e; }
        }
        float s = 0.f, p[E_NUM];
#pragma unroll
        for (int e = 0; e < E_NUM; e++) { p[e] = expf(lg[e] - mx); s += p[e]; }
        float inv = 1.f / s;
#pragma unroll
        for (int e = 0; e < E_NUM; e++) { p[e] *= inv; s_p[warp][e] = p[e]; }
        g_prob[t] = p[am];
        int pos = atomicAdd(&g_cnt[am], 1);
        g_idx[am * T_TOK + pos] = t;
    }
    __syncthreads();
    if (threadIdx.x < E_NUM) {
        int e = threadIdx.x;
        float s = 0.f;
#pragma unroll
        for (int w = 0; w < 8; w++) s += s_p[w][e];
        g_partial[blockIdx.x * E_NUM + e] = s;
    }
}

// ---------------------------------------------------------------------------
// Aux loss: parallel deterministic reduction.
__global__ void aux_kernel(float* __restrict__ out, int out_size) {
    __shared__ float s_e[E_NUM];
    int wid = threadIdx.x >> 5;
    int lane = threadIdx.x & 31;
    if (wid < E_NUM) {
        float s = 0.f;
#pragma unroll
        for (int j = 0; j < ROUTER_BLOCKS / 32; j++)
            s += g_partial[(j * 32 + lane) * E_NUM + wid];
#pragma unroll
        for (int o = 16; o > 0; o >>= 1)
            s += __shfl_xor_sync(0xffffffffu, s, o);
        if (lane == 0) {
            float imp = s * (1.f / (float)T_TOK);
            float load = (float)g_cnt[wid] * (1.f / (float)T_TOK);
            s_e[wid] = imp * load;
        }
    }
    __syncthreads();
    if (threadIdx.x == 0) {
        float a = 0.f;
        for (int e = 0; e < E_NUM; e++) a += s_e[e];
        out[out_size - 1] = (float)E_NUM * a;
    }
}

// ===========================================================================
// bf16 split GEMM with warp-level mma.sync (HMMA).
// 256 threads, 8 warps (4 M x 2 N), warp tile 32x64, CTA tile 128x128x64,
// double-buffered SMEM, one barrier per 64-K iteration.
// ===========================================================================
#define LDSM4(r, a) \
    asm volatile("ldmatrix.sync.aligned.m8n8.x4.shared.b16 {%0,%1,%2,%3}, [%4];" \
        : "=r"((r)[0]), "=r"((r)[1]), "=r"((r)[2]), "=r"((r)[3]) : "r"(a))
#define LDSM4T(r, a) \
    asm volatile("ldmatrix.sync.aligned.m8n8.x4.trans.shared.b16 {%0,%1,%2,%3}, [%4];" \
        : "=r"((r)[0]), "=r"((r)[1]), "=r"((r)[2]), "=r"((r)[3]) : "r"(a))
#define MMA16816(d, a, b0, b1) \
    asm volatile("mma.sync.aligned.m16n8k16.row.col.f32.bf16.bf16.f32 " \
        "{%0,%1,%2,%3}, {%4,%5,%6,%7}, {%8,%9}, {%0,%1,%2,%3};" \
        : "+f"((d)[0]), "+f"((d)[1]), "+f"((d)[2]), "+f"((d)[3]) \
        : "r"((a)[0]), "r"((a)[1]), "r"((a)[2]), "r"((a)[3]), "r"(b0), "r"(b1))

__device__ __forceinline__ uint32_t sptr(const void* p) {
    return (uint32_t)__cvta_generic_to_shared(p);
}

// Convert float4 -> bf16 hi pair + lo pair (hi=truncate, lo=rn(residual)).
__device__ __forceinline__ void cvt_store(char* hip, char* lop, float4 f) {
    uint32_t h0, h1, l0, l1;
    asm("prmt.b32 %0, %1, %2, 0x7632;" : "=r"(h0)
        : "r"(__float_as_uint(f.x)), "r"(__float_as_uint(f.y)));
    asm("prmt.b32 %0, %1, %2, 0x7632;" : "=r"(h1)
        : "r"(__float_as_uint(f.z)), "r"(__float_as_uint(f.w)));
    float r0 = f.x - __uint_as_float(__float_as_uint(f.x) & 0xffff0000u);
    float r1 = f.y - __uint_as_float(__float_as_uint(f.y) & 0xffff0000u);
    float r2 = f.z - __uint_as_float(__float_as_uint(f.z) & 0xffff0000u);
    float r3 = f.w - __uint_as_float(__float_as_uint(f.w) & 0xffff0000u);
    asm("cvt.rn.bf16x2.f32 %0, %1, %2;" : "=r"(l0) : "f"(r1), "f"(r0));
    asm("cvt.rn.bf16x2.f32 %0, %1, %2;" : "=r"(l1) : "f"(r3), "f"(r2));
    *(uint2*)hip = make_uint2(h0, h1);
    *(uint2*)lop = make_uint2(l0, l1);
}

// Tile geometry
#define BM 128
#define BN 128
#define BKK 64
#define NTHREADS 256
#define ASTR 72    // padded A row (64 + 8 bf16 elems) -> bank-safe
#define BSTR 136   // padded B row (128 + 8 bf16 elems)

// Dynamic SMEM layout (one buffer; two buffers back-to-back)
#define ASZ   (BM * ASTR * 2)          // 18432 bytes per plane
#define BSZ   (BKK * BSTR * 2)         // 17408 bytes per plane
#define O_AH  0
#define O_AL  (O_AH + ASZ)
#define O_BH  (O_AL + ASZ)
#define O_BL  (O_BH + BSZ)
#define BUF_BYTES (2 * ASZ + 2 * BSZ)  // 71680
#define DYN_SMEM  (2 * BUF_BYTES)      // 143360

// FFN1: D = silu(x @ w1 + b1) -> g_h ; FFN2: D = (h @ w2 + b2)*prob -> out
template<int K_TOTAL, int A_STRIDE, int B_STRIDE, bool FFN1>
__global__ void __launch_bounds__(NTHREADS, 1)
ffn_mma_kernel(const float* __restrict__ Asrc, const float* __restrict__ Bsrc,
               const float* __restrict__ bias, float* __restrict__ Dst) {
    const int e = blockIdx.y;
    const int cnt = g_cnt[e];
    const int m0 = blockIdx.z * BM;
    if (m0 >= cnt) return;
    const int n0 = blockIdx.x * BN;

    extern __shared__ __align__(16) char dsm[];
    __shared__ int toks_s[BM];

    const int tid = threadIdx.x;
    const int wid = tid >> 5;
    const int lane = tid & 31;
    const int warp_m = wid >> 1;   // 0..3  (32 rows each)
    const int warp_n = wid & 1;    // 0..1  (64 cols each)

    if (tid < BM) {
        int m = m0 + tid;
        toks_s[tid] = (m < cnt) ? g_idx[e * T_TOK + m] : -1;
    }
    __syncthreads();

    // loader mapping:
    // A tile 128x64: 2 threads/row, each 32 floats (8 float4 consecutive)
    const int a_row = tid >> 1;
    const int a_cg  = (tid & 1) * 32;
    const int tokA  = toks_s[a_row];
    const float* arow = (tokA >= 0) ? (Asrc + (size_t)tokA * A_STRIDE) : nullptr;
    // B tile 64x128: 4 threads/row, each 32 floats strided (4 floats every 16)
    const int b_row = tid >> 2;          // 0..63 (k within tile)
    const int b_c4  = (tid & 3) * 4;     // 0,4,8,12
    const float* brow = Bsrc + (size_t)e * K_TOTAL * B_STRIDE
                       + (size_t)b_row * B_STRIDE + n0 + b_c4;

    const uint32_t a_sts = (uint32_t)((a_row * ASTR + a_cg) * 2);
    const uint32_t b_sts = (uint32_t)((b_row * BSTR + b_c4) * 2);

    float4 ra[8], rb[8];
#define LDG_TILE(k0) do { \
    _Pragma("unroll") \
    for (int j = 0; j < 8; j++) { \
        ra[j] = arow ? *(const float4*)(arow + (k0) + a_cg + j * 4) \
                     : make_float4(0.f, 0.f, 0.f, 0.f); \
        rb[j] = *(const float4*)(brow + (size_t)(k0) * B_STRIDE + j * 16); \
    } \
} while (0)
#define STS_TILE(base) do { \
    _Pragma("unroll") \
    for (int j = 0; j < 8; j++) { \
        cvt_store((base) + O_AH + a_sts + j * 16, (base) + O_AL + a_sts + j * 16, ra[j]); \
        cvt_store((base) + O_BH + b_sts + j * 32 * 2 * 2, \
                  (base) + O_BL + b_sts + j * 32 * 2 * 2, rb[j]); \
    } \
} while (0)
    // note: B col step per j = 16 floats = 32 bf16 = 64 bytes -> j*64? careful:
    // rb[j] holds floats at col b_c4 + j*16 -> byte offset (b_c4 + j*16)*2.
    // b_sts already includes b_c4*2, so add j*16*2 = j*32 bytes.
#undef STS_TILE
#define STS_TILE(base) do { \
    _Pragma("unroll") \
    for (int j = 0; j < 8; j++) { \
        cvt_store((base) + O_AH + a_sts + j * 8, (base) + O_AL + a_sts + j * 8, ra[j]); \
        cvt_store((base) + O_BH + b_sts + j * 32, (base) + O_BL + b_sts + j * 32, rb[j]); \
    } \
} while (0)

    // prologue: iter 0 -> buffer 0, prefetch iter 1
    LDG_TILE(0);
    STS_TILE(dsm);
    if (K_TOTAL > BKK) LDG_TILE(BKK);
    __syncthreads();

    float acc[2][8][4];
#pragma unroll
    for (int mi = 0; mi < 2; mi++)
#pragma unroll
        for (int nj = 0; nj < 8; nj++)
#pragma unroll
            for (int q = 0; q < 4; q++) acc[mi][nj][q] = 0.f;

    const uint32_t dynb = sptr(dsm);
    const int lm  = lane & 15;
    const int lg8 = (lane >> 4) * 8;
    const uint32_t aoff = (uint32_t)(((warp_m * 32 + lm) * ASTR + lg8) * 2);
    const uint32_t boff = (uint32_t)((lm * BSTR + warp_n * 64 + lg8) * 2);

    const int n_iters = K_TOTAL / BKK;
    for (int it = 0; it < n_iters; ++it) {
        const int cur = it & 1;

        // STS iter it+1 into the other buffer
        if (it + 1 < n_iters) {
            char* nb = dsm + (cur ^ 1) * BUF_BYTES;
            STS_TILE(nb);
        }
        // LDG iter it+2 into registers
        if (it + 2 < n_iters) LDG_TILE((it + 2) * BKK);

        // compute current buffer: 4 x k16 steps, 3-term bf16 split,
        // B fragments staged in 32-col halves.
        const uint32_t aH = dynb + cur * BUF_BYTES + O_AH;
        const uint32_t aL = dynb + cur * BUF_BYTES + O_AL;
        const uint32_t bH = dynb + cur * BUF_BYTES + O_BH;
        const uint32_t bL = dynb + cur * BUF_BYTES + O_BL;
#pragma unroll
        for (int kk = 0; kk < 4; kk++) {
            uint32_t fah[2][4], fal[2][4];
#pragma unroll
            for (int mi = 0; mi < 2; mi++) {
                uint32_t aa = aoff + (uint32_t)((mi * 16 * ASTR + kk * 16) * 2);
                LDSM4(fah[mi], aH + aa);
                LDSM4(fal[mi], aL + aa);
            }
#pragma unroll
            for (int h2 = 0; h2 < 2; h2++) {
                uint32_t fbh[2][4], fbl[2][4];
#pragma unroll
                for (int ni = 0; ni < 2; ni++) {
                    uint32_t ba = boff + (uint32_t)((kk * 16 * BSTR + h2 * 32 + ni * 16) * 2);
                    LDSM4T(fbh[ni], bH + ba);
                    LDSM4T(fbl[ni], bL + ba);
                }
#pragma unroll
                for (int mi = 0; mi < 2; mi++) {
#pragma unroll
                    for (int nl = 0; nl < 4; nl++) {
                        int nj = h2 * 4 + nl;
                        uint32_t b0h = fbh[nl >> 1][(nl & 1) * 2];
                        uint32_t b1h = fbh[nl >> 1][(nl & 1) * 2 + 1];
                        uint32_t b0l = fbl[nl >> 1][(nl & 1) * 2];
                        uint32_t b1l = fbl[nl >> 1][(nl & 1) * 2 + 1];
                        MMA16816(acc[mi][nj], fah[mi], b0h, b1h);
                        MMA16816(acc[mi][nj], fah[mi], b0l, b1l);
                        MMA16816(acc[mi][nj], fal[mi], b0h, b1h);
                    }
                }
            }
        }
        __syncthreads();
    }

    // epilogue: straight from registers
    const int r4 = lane >> 2;
    const int c2 = (lane & 3) * 2;
    const float* bias_p = bias + (size_t)e * B_STRIDE + n0 + warp_n * 64;
#pragma unroll
    for (int mi = 0; mi < 2; mi++) {
#pragma unroll
        for (int half = 0; half < 2; half++) {
            int rl = warp_m * 32 + mi * 16 + half * 8 + r4;
            int tok = toks_s[rl];
            if (tok < 0) continue;
            float p = 1.f;
            if (!FFN1) p = g_prob[tok];
            float* drow = Dst + (size_t)tok * B_STRIDE + n0 + warp_n * 64;
#pragma unroll
            for (int nj = 0; nj < 8; nj++) {
                int c = nj * 8 + c2;
                float v0 = acc[mi][nj][half * 2 + 0] + bias_p[c];
                float v1 = acc[mi][nj][half * 2 + 1] + bias_p[c + 1];
                float2 o;
                if (FFN1) {
                    o.x = v0 / (1.f + expf(-v0));
                    o.y = v1 / (1.f + expf(-v1));
                } else {
                    o.x = v0 * p;
                    o.y = v1 * p;
                }
                *(float2*)(drow + c) = o;
            }
        }
    }
}

// ---------------------------------------------------------------------------
extern "C" void kernel_launch(void* const* d_in, const int* in_sizes, int n_in,
                              void* d_out, int out_size) {
    const float* x  = (const float*)d_in[0];
    const float* rw = (const float*)d_in[1];
    const float* rb = (const float*)d_in[2];
    const float* w1 = (const float*)d_in[3];
    const float* b1 = (const float*)d_in[4];
    const float* w2 = (const float*)d_in[5];
    const float* b2 = (const float*)d_in[6];
    float* out = (float*)d_out;

    cudaFuncSetAttribute(ffn_mma_kernel<C_DIM, C_DIM, F_DIM, true>,
                         cudaFuncAttributeMaxDynamicSharedMemorySize, DYN_SMEM);
    cudaFuncSetAttribute(ffn_mma_kernel<F_DIM, F_DIM, C_DIM, false>,
                         cudaFuncAttributeMaxDynamicSharedMemorySize, DYN_SMEM);

    float* h = nullptr;
    cudaGetSymbolAddress((void**)&h, g_h);

    init_kernel<<<1, 32>>>();
    router_kernel<<<ROUTER_BLOCKS, 256>>>(x, rw, rb);
    aux_kernel<<<1, 256>>>(out, out_size);

    // FFN1: [cnt_e,1024] @ [1024,4096] -> silu -> g_h
    ffn_mma_kernel<C_DIM, C_DIM, F_DIM, true>
        <<<dim3(F_DIM / BN, E_NUM, T_TOK / BM), NTHREADS, DYN_SMEM>>>(x, w1, b1, h);
    // FFN2: [cnt_e,4096] @ [4096,1024] -> *prob -> out
    ffn_mma_kernel<F_DIM, F_DIM, C_DIM, false>
        <<<dim3(C_DIM / BN, E_NUM, T_TOK / BM), NTHREADS, DYN_SMEM>>>(h, w2, b2, out);
}

// round 8
// speedup vs baseline: 2.4810x; 1.1727x over previous
#include <cuda_runtime.h>
#include <cuda_bf16.h>
#include <math.h>
#include <stdint.h>

// Problem constants
#define T_TOK 2048
#define C_DIM 1024
#define F_DIM 4096
#define E_NUM 8
#define ROUTER_BLOCKS 256   // 8 tokens (warps) per block

// Scratch (allocation-free rule: __device__ globals)
__device__ int   g_cnt[E_NUM];
__device__ int   g_idx[E_NUM * T_TOK];
__device__ float g_prob[T_TOK];
__device__ float g_partial[ROUTER_BLOCKS * E_NUM];
__device__ float g_h[(size_t)T_TOK * F_DIM];   // 33.5 MB intermediate, keyed by token id

// ---------------------------------------------------------------------------
__global__ void init_kernel() {
    int i = threadIdx.x;
    if (i < E_NUM) g_cnt[i] = 0;
}

// ---------------------------------------------------------------------------
// Router: one warp per token. Deterministic importance partials per block.
__global__ void router_kernel(const float* __restrict__ x,
                              const float* __restrict__ rw,
                              const float* __restrict__ rb) {
    int warp = threadIdx.x >> 5;
    int lane = threadIdx.x & 31;
    int t = blockIdx.x * 8 + warp;

    float acc[E_NUM];
#pragma unroll
    for (int e = 0; e < E_NUM; e++) acc[e] = 0.f;

    const float* xr = x + (size_t)t * C_DIM;
    for (int c = lane; c < C_DIM; c += 32) {
        float xv = xr[c];
        const float4* r = (const float4*)(rw + c * E_NUM);
        float4 r0 = r[0];
        float4 r1 = r[1];
        acc[0] += xv * r0.x; acc[1] += xv * r0.y;
        acc[2] += xv * r0.z; acc[3] += xv * r0.w;
        acc[4] += xv * r1.x; acc[5] += xv * r1.y;
        acc[6] += xv * r1.z; acc[7] += xv * r1.w;
    }
#pragma unroll
    for (int e = 0; e < E_NUM; e++) {
#pragma unroll
        for (int o = 16; o > 0; o >>= 1)
            acc[e] += __shfl_xor_sync(0xffffffffu, acc[e], o);
    }

    __shared__ float s_p[8][E_NUM];
    if (lane == 0) {
        float lg[E_NUM];
        float mx = -1e30f; int am = 0;
#pragma unroll
        for (int e = 0; e < E_NUM; e++) {
            lg[e] = acc[e] + rb[e];
            if (lg[e] > mx) { mx = lg[e]; am = e; }
        }
        float s = 0.f, p[E_NUM];
#pragma unroll
        for (int e = 0; e < E_NUM; e++) { p[e] = expf(lg[e] - mx); s += p[e]; }
        float inv = 1.f / s;
#pragma unroll
        for (int e = 0; e < E_NUM; e++) { p[e] *= inv; s_p[warp][e] = p[e]; }
        g_prob[t] = p[am];
        int pos = atomicAdd(&g_cnt[am], 1);
        g_idx[am * T_TOK + pos] = t;
    }
    __syncthreads();
    if (threadIdx.x < E_NUM) {
        int e = threadIdx.x;
        float s = 0.f;
#pragma unroll
        for (int w = 0; w < 8; w++) s += s_p[w][e];
        g_partial[blockIdx.x * E_NUM + e] = s;
    }
}

// ---------------------------------------------------------------------------
// Aux loss: parallel deterministic reduction.
__global__ void aux_kernel(float* __restrict__ out, int out_size) {
    __shared__ float s_e[E_NUM];
    int wid = threadIdx.x >> 5;
    int lane = threadIdx.x & 31;
    if (wid < E_NUM) {
        float s = 0.f;
#pragma unroll
        for (int j = 0; j < ROUTER_BLOCKS / 32; j++)
            s += g_partial[(j * 32 + lane) * E_NUM + wid];
#pragma unroll
        for (int o = 16; o > 0; o >>= 1)
            s += __shfl_xor_sync(0xffffffffu, s, o);
        if (lane == 0) {
            float imp = s * (1.f / (float)T_TOK);
            float load = (float)g_cnt[wid] * (1.f / (float)T_TOK);
            s_e[wid] = imp * load;
        }
    }
    __syncthreads();
    if (threadIdx.x == 0) {
        float a = 0.f;
        for (int e = 0; e < E_NUM; e++) a += s_e[e];
        out[out_size - 1] = (float)E_NUM * a;
    }
}

// ===========================================================================
// bf16 split GEMM with warp-level mma.sync (HMMA).
// Warp tile fixed 32x32; CTA tile BMT x BNT templated; BKK=32;
// double-buffered SMEM, one barrier per K-iteration.
// ===========================================================================
#define LDSM4(r, a) \
    asm volatile("ldmatrix.sync.aligned.m8n8.x4.shared.b16 {%0,%1,%2,%3}, [%4];" \
        : "=r"((r)[0]), "=r"((r)[1]), "=r"((r)[2]), "=r"((r)[3]) : "r"(a))
#define LDSM4T(r, a) \
    asm volatile("ldmatrix.sync.aligned.m8n8.x4.trans.shared.b16 {%0,%1,%2,%3}, [%4];" \
        : "=r"((r)[0]), "=r"((r)[1]), "=r"((r)[2]), "=r"((r)[3]) : "r"(a))
#define MMA16816(d, a, b0, b1) \
    asm volatile("mma.sync.aligned.m16n8k16.row.col.f32.bf16.bf16.f32 " \
        "{%0,%1,%2,%3}, {%4,%5,%6,%7}, {%8,%9}, {%0,%1,%2,%3};" \
        : "+f"((d)[0]), "+f"((d)[1]), "+f"((d)[2]), "+f"((d)[3]) \
        : "r"((a)[0]), "r"((a)[1]), "r"((a)[2]), "r"((a)[3]), "r"(b0), "r"(b1))

__device__ __forceinline__ uint32_t sptr(const void* p) {
    return (uint32_t)__cvta_generic_to_shared(p);
}

// Convert float4 -> bf16 hi pair + lo pair (hi=truncate, lo=rn(residual)).
__device__ __forceinline__ void cvt_store(char* hip, char* lop, float4 f) {
    uint32_t h0, h1, l0, l1;
    asm("prmt.b32 %0, %1, %2, 0x7632;" : "=r"(h0)
        : "r"(__float_as_uint(f.x)), "r"(__float_as_uint(f.y)));
    asm("prmt.b32 %0, %1, %2, 0x7632;" : "=r"(h1)
        : "r"(__float_as_uint(f.z)), "r"(__float_as_uint(f.w)));
    float r0 = f.x - __uint_as_float(__float_as_uint(f.x) & 0xffff0000u);
    float r1 = f.y - __uint_as_float(__float_as_uint(f.y) & 0xffff0000u);
    float r2 = f.z - __uint_as_float(__float_as_uint(f.z) & 0xffff0000u);
    float r3 = f.w - __uint_as_float(__float_as_uint(f.w) & 0xffff0000u);
    asm("cvt.rn.bf16x2.f32 %0, %1, %2;" : "=r"(l0) : "f"(r1), "f"(r0));
    asm("cvt.rn.bf16x2.f32 %0, %1, %2;" : "=r"(l1) : "f"(r3), "f"(r2));
    *(uint2*)hip = make_uint2(h0, h1);
    *(uint2*)lop = make_uint2(l0, l1);
}

#define BKK 32
#define ASTR 40    // padded A row (32 + 8 bf16 elems)

// FFN1: D = silu(x @ w1 + b1) -> g_h ; FFN2: D = (h @ w2 + b2)*prob -> out
template<int K_TOTAL, int A_STRIDE, int B_STRIDE, bool FFN1,
         int BMT, int BNT, int NT, int MINB>
__global__ void __launch_bounds__(NT, MINB)
ffn_mma_kernel(const float* __restrict__ Asrc, const float* __restrict__ Bsrc,
               const float* __restrict__ bias, float* __restrict__ Dst) {
    constexpr int BSTR = BNT + 8;
    constexpr int ASZ  = BMT * ASTR * 2;
    constexpr int BSZ  = BKK * BSTR * 2;
    constexpr int O_AH = 0;
    constexpr int O_AL = O_AH + ASZ;
    constexpr int O_BH = O_AL + ASZ;
    constexpr int O_BL = O_BH + BSZ;
    constexpr int BUF_BYTES = 2 * ASZ + 2 * BSZ;
    constexpr int NWN  = BNT / 32;            // warps along N
    constexpr int TPRA = NT / BMT;            // threads per A row
    constexpr int AF4  = 32 / TPRA / 4;       // float4 per thread (A)
    constexpr int TPRB = NT / BKK;            // threads per B row
    constexpr int BF4  = BNT / TPRB / 4;      // float4 per thread (B)

    const int e = blockIdx.y;
    const int cnt = g_cnt[e];
    const int m0 = blockIdx.z * BMT;
    if (m0 >= cnt) return;
    const int n0 = blockIdx.x * BNT;

    extern __shared__ __align__(16) char dsm[];
    __shared__ int toks_s[BMT];

    const int tid = threadIdx.x;
    const int wid = tid >> 5;
    const int lane = tid & 31;
    const int warp_m = wid / NWN;
    const int warp_n = wid % NWN;

    if (tid < BMT) {
        int m = m0 + tid;
        toks_s[tid] = (m < cnt) ? g_idx[e * T_TOK + m] : -1;
    }
    __syncthreads();

    // loader mapping
    const int a_row = tid / TPRA;
    const int a_cg  = (tid % TPRA) * (32 / TPRA);
    const int tokA  = toks_s[a_row];
    const float* arow = (tokA >= 0) ? (Asrc + (size_t)tokA * A_STRIDE) : nullptr;
    const int b_row = tid / TPRB;
    const int b_cg  = (tid % TPRB) * (BNT / TPRB);
    const float* brow = Bsrc + (size_t)e * K_TOTAL * B_STRIDE
                       + (size_t)b_row * B_STRIDE + n0 + b_cg;

    const uint32_t a_sts = (uint32_t)((a_row * ASTR + a_cg) * 2);
    const uint32_t b_sts = (uint32_t)((b_row * BSTR + b_cg) * 2);

    float4 ra[AF4], rb[BF4];
    // prologue: LDG iter 0
#pragma unroll
    for (int j = 0; j < AF4; j++)
        ra[j] = arow ? *(const float4*)(arow + a_cg + j * 4)
                     : make_float4(0.f, 0.f, 0.f, 0.f);
#pragma unroll
    for (int j = 0; j < BF4; j++)
        rb[j] = *(const float4*)(brow + j * 4);
    // STS iter 0 -> buffer 0
#pragma unroll
    for (int j = 0; j < AF4; j++)
        cvt_store(dsm + O_AH + a_sts + j * 8, dsm + O_AL + a_sts + j * 8, ra[j]);
#pragma unroll
    for (int j = 0; j < BF4; j++)
        cvt_store(dsm + O_BH + b_sts + j * 8, dsm + O_BL + b_sts + j * 8, rb[j]);
    // LDG iter 1
    if (K_TOTAL > BKK) {
#pragma unroll
        for (int j = 0; j < AF4; j++)
            ra[j] = arow ? *(const float4*)(arow + BKK + a_cg + j * 4)
                         : make_float4(0.f, 0.f, 0.f, 0.f);
#pragma unroll
        for (int j = 0; j < BF4; j++)
            rb[j] = *(const float4*)(brow + (size_t)BKK * B_STRIDE + j * 4);
    }
    __syncthreads();

    float acc[2][4][4];
#pragma unroll
    for (int mi = 0; mi < 2; mi++)
#pragma unroll
        for (int nj = 0; nj < 4; nj++)
#pragma unroll
            for (int q = 0; q < 4; q++) acc[mi][nj][q] = 0.f;

    const uint32_t dynb = sptr(dsm);
    const int lm  = lane & 15;
    const int lg8 = (lane >> 4) * 8;
    const uint32_t aoff = (uint32_t)(((warp_m * 32 + lm) * ASTR + lg8) * 2);
    const uint32_t boff = (uint32_t)((lm * BSTR + warp_n * 32 + lg8) * 2);

    const int n_iters = K_TOTAL / BKK;
    for (int it = 0; it < n_iters; ++it) {
        const int cur = it & 1;

        // STS iter it+1 into the other buffer
        if (it + 1 < n_iters) {
            char* nb = dsm + (cur ^ 1) * BUF_BYTES;
#pragma unroll
            for (int j = 0; j < AF4; j++)
                cvt_store(nb + O_AH + a_sts + j * 8, nb + O_AL + a_sts + j * 8, ra[j]);
#pragma unroll
            for (int j = 0; j < BF4; j++)
                cvt_store(nb + O_BH + b_sts + j * 8, nb + O_BL + b_sts + j * 8, rb[j]);
        }
        // LDG iter it+2 into registers
        if (it + 2 < n_iters) {
            const int k0 = (it + 2) * BKK;
#pragma unroll
            for (int j = 0; j < AF4; j++)
                ra[j] = arow ? *(const float4*)(arow + k0 + a_cg + j * 4)
                             : make_float4(0.f, 0.f, 0.f, 0.f);
#pragma unroll
            for (int j = 0; j < BF4; j++)
                rb[j] = *(const float4*)(brow + (size_t)k0 * B_STRIDE + j * 4);
        }

        // compute current buffer: 2 x k16 steps, 3-term bf16 split
        const uint32_t aH = dynb + cur * BUF_BYTES + O_AH;
        const uint32_t aL = dynb + cur * BUF_BYTES + O_AL;
        const uint32_t bH = dynb + cur * BUF_BYTES + O_BH;
        const uint32_t bL = dynb + cur * BUF_BYTES + O_BL;
#pragma unroll
        for (int kk = 0; kk < 2; kk++) {
            uint32_t fah[2][4], fal[2][4], fbh[2][4], fbl[2][4];
#pragma unroll
            for (int ni = 0; ni < 2; ni++) {
                uint32_t ba = boff + (uint32_t)((kk * 16 * BSTR + ni * 16) * 2);
                LDSM4T(fbh[ni], bH + ba);
                LDSM4T(fbl[ni], bL + ba);
            }
#pragma unroll
            for (int mi = 0; mi < 2; mi++) {
                uint32_t aa = aoff + (uint32_t)((mi * 16 * ASTR + kk * 16) * 2);
                LDSM4(fah[mi], aH + aa);
                LDSM4(fal[mi], aL + aa);
            }
#pragma unroll
            for (int mi = 0; mi < 2; mi++) {
#pragma unroll
                for (int nj = 0; nj < 4; nj++) {
                    uint32_t b0h = fbh[nj >> 1][(nj & 1) * 2];
                    uint32_t b1h = fbh[nj >> 1][(nj & 1) * 2 + 1];
                    uint32_t b0l = fbl[nj >> 1][(nj & 1) * 2];
                    uint32_t b1l = fbl[nj >> 1][(nj & 1) * 2 + 1];
                    MMA16816(acc[mi][nj], fah[mi], b0h, b1h);
                    MMA16816(acc[mi][nj], fah[mi], b0l, b1l);
                    MMA16816(acc[mi][nj], fal[mi], b0h, b1h);
                }
            }
        }
        __syncthreads();
    }

    // epilogue: straight from registers
    const int r4 = lane >> 2;
    const int c2 = (lane & 3) * 2;
    const float* bias_p = bias + (size_t)e * B_STRIDE + n0 + warp_n * 32;
#pragma unroll
    for (int mi = 0; mi < 2; mi++) {
#pragma unroll
        for (int half = 0; half < 2; half++) {
            int rl = warp_m * 32 + mi * 16 + half * 8 + r4;
            int tok = toks_s[rl];
            if (tok < 0) continue;
            float p = 1.f;
            if (!FFN1) p = g_prob[tok];
            float* drow = Dst + (size_t)tok * B_STRIDE + n0 + warp_n * 32;
#pragma unroll
            for (int nj = 0; nj < 4; nj++) {
                int c = nj * 8 + c2;
                float v0 = acc[mi][nj][half * 2 + 0] + bias_p[c];
                float v1 = acc[mi][nj][half * 2 + 1] + bias_p[c + 1];
                float2 o;
                if (FFN1) {
                    o.x = v0 / (1.f + expf(-v0));
                    o.y = v1 / (1.f + expf(-v1));
                } else {
                    o.x = v0 * p;
                    o.y = v1 * p;
                }
                *(float2*)(drow + c) = o;
            }
        }
    }
}

// ---------------------------------------------------------------------------
// Instantiation parameters
// FFN1: BM=128, BN=128, 512 threads (16 warps, 4x4)
// FFN2: BM=64,  BN=64,  128 threads (4 warps, 2x2) -> many small CTAs
#define F1_SMEM (2 * (2 * (128 * ASTR * 2) + 2 * (BKK * (128 + 8) * 2)))
#define F2_SMEM (2 * (2 * (64 * ASTR * 2) + 2 * (BKK * (64 + 8) * 2)))

extern "C" void kernel_launch(void* const* d_in, const int* in_sizes, int n_in,
                              void* d_out, int out_size) {
    const float* x  = (const float*)d_in[0];
    const float* rw = (const float*)d_in[1];
    const float* rb = (const float*)d_in[2];
    const float* w1 = (const float*)d_in[3];
    const float* b1 = (const float*)d_in[4];
    const float* w2 = (const float*)d_in[5];
    const float* b2 = (const float*)d_in[6];
    float* out = (float*)d_out;

    cudaFuncSetAttribute(
        ffn_mma_kernel<C_DIM, C_DIM, F_DIM, true, 128, 128, 512, 1>,
        cudaFuncAttributeMaxDynamicSharedMemorySize, F1_SMEM);
    cudaFuncSetAttribute(
        ffn_mma_kernel<F_DIM, F_DIM, C_DIM, false, 64, 64, 128, 2>,
        cudaFuncAttributeMaxDynamicSharedMemorySize, F2_SMEM);

    float* h = nullptr;
    cudaGetSymbolAddress((void**)&h, g_h);

    init_kernel<<<1, 32>>>();
    router_kernel<<<ROUTER_BLOCKS, 256>>>(x, rw, rb);
    aux_kernel<<<1, 256>>>(out, out_size);

    // FFN1: [cnt_e,1024] @ [1024,4096] -> silu -> g_h
    ffn_mma_kernel<C_DIM, C_DIM, F_DIM, true, 128, 128, 512, 1>
        <<<dim3(F_DIM / 128, E_NUM, T_TOK / 128), 512, F1_SMEM>>>(x, w1, b1, h);
    // FFN2: [cnt_e,4096] @ [4096,1024] -> *prob -> out (64x64 tiles for occupancy)
    ffn_mma_kernel<F_DIM, F_DIM, C_DIM, false, 64, 64, 128, 2>
        <<<dim3(C_DIM / 64, E_NUM, T_TOK / 64), 128, F2_SMEM>>>(h, w2, b2, out);
}

// round 9
// speedup vs baseline: 2.9072x; 1.1718x over previous
#include <cuda_runtime.h>
#include <cuda_bf16.h>
#include <cuda_fp16.h>
#include <math.h>
#include <stdint.h>

// Problem constants
#define T_TOK 2048
#define C_DIM 1024
#define F_DIM 4096
#define E_NUM 8
#define ROUTER_BLOCKS 256   // 8 tokens (warps) per block

// Scratch (allocation-free rule: __device__ globals)
__device__ int   g_cnt[E_NUM];
__device__ int   g_idx[E_NUM * T_TOK];
__device__ float g_prob[T_TOK];
__device__ float g_partial[ROUTER_BLOCKS * E_NUM];
__device__ float g_h[(size_t)T_TOK * F_DIM];   // 33.5 MB intermediate, keyed by token id

// ---------------------------------------------------------------------------
__global__ void init_kernel() {
    int i = threadIdx.x;
    if (i < E_NUM) g_cnt[i] = 0;
}

// ---------------------------------------------------------------------------
// Router: one warp per token. Deterministic importance partials per block.
__global__ void router_kernel(const float* __restrict__ x,
                              const float* __restrict__ rw,
                              const float* __restrict__ rb) {
    int warp = threadIdx.x >> 5;
    int lane = threadIdx.x & 31;
    int t = blockIdx.x * 8 + warp;

    float acc[E_NUM];
#pragma unroll
    for (int e = 0; e < E_NUM; e++) acc[e] = 0.f;

    const float* xr = x + (size_t)t * C_DIM;
    for (int c = lane; c < C_DIM; c += 32) {
        float xv = xr[c];
        const float4* r = (const float4*)(rw + c * E_NUM);
        float4 r0 = r[0];
        float4 r1 = r[1];
        acc[0] += xv * r0.x; acc[1] += xv * r0.y;
        acc[2] += xv * r0.z; acc[3] += xv * r0.w;
        acc[4] += xv * r1.x; acc[5] += xv * r1.y;
        acc[6] += xv * r1.z; acc[7] += xv * r1.w;
    }
#pragma unroll
    for (int e = 0; e < E_NUM; e++) {
#pragma unroll
        for (int o = 16; o > 0; o >>= 1)
            acc[e] += __shfl_xor_sync(0xffffffffu, acc[e], o);
    }

    __shared__ float s_p[8][E_NUM];
    if (lane == 0) {
        float lg[E_NUM];
        float mx = -1e30f; int am = 0;
#pragma unroll
        for (int e = 0; e < E_NUM; e++) {
            lg[e] = acc[e] + rb[e];
            if (lg[e] > mx) { mx = lg[e]; am = e; }
        }
        float s = 0.f, p[E_NUM];
#pragma unroll
        for (int e = 0; e < E_NUM; e++) { p[e] = expf(lg[e] - mx); s += p[e]; }
        float inv = 1.f / s;
#pragma unroll
        for (int e = 0; e < E_NUM; e++) { p[e] *= inv; s_p[warp][e] = p[e]; }
        g_prob[t] = p[am];
        int pos = atomicAdd(&g_cnt[am], 1);
        g_idx[am * T_TOK + pos] = t;
    }
    __syncthreads();
    if (threadIdx.x < E_NUM) {
        int e = threadIdx.x;
        float s = 0.f;
#pragma unroll
        for (int w = 0; w < 8; w++) s += s_p[w][e];
        g_partial[blockIdx.x * E_NUM + e] = s;
    }
}

// ---------------------------------------------------------------------------
// Aux loss: parallel deterministic reduction.
__global__ void aux_kernel(float* __restrict__ out, int out_size) {
    __shared__ float s_e[E_NUM];
    int wid = threadIdx.x >> 5;
    int lane = threadIdx.x & 31;
    if (wid < E_NUM) {
        float s = 0.f;
#pragma unroll
        for (int j = 0; j < ROUTER_BLOCKS / 32; j++)
            s += g_partial[(j * 32 + lane) * E_NUM + wid];
#pragma unroll
        for (int o = 16; o > 0; o >>= 1)
            s += __shfl_xor_sync(0xffffffffu, s, o);
        if (lane == 0) {
            float imp = s * (1.f / (float)T_TOK);
            float load = (float)g_cnt[wid] * (1.f / (float)T_TOK);
            s_e[wid] = imp * load;
        }
    }
    __syncthreads();
    if (threadIdx.x == 0) {
        float a = 0.f;
        for (int e = 0; e < E_NUM; e++) a += s_e[e];
        out[out_size - 1] = (float)E_NUM * a;
    }
}

// ===========================================================================
// fp16 2-term split GEMM with warp-level mma.sync (HMMA).
// A = Ah + Al (both fp16, reproduces fp32 to ~2^-22); B = fp16(B).
// D = Ah*Bh + Al*Bh  (2 MMAs per k16). Warp tile 32x32; BKK=32;
// double-buffered SMEM, one barrier per K-iteration.
// ===========================================================================
#define LDSM4(r, a) \
    asm volatile("ldmatrix.sync.aligned.m8n8.x4.shared.b16 {%0,%1,%2,%3}, [%4];" \
        : "=r"((r)[0]), "=r"((r)[1]), "=r"((r)[2]), "=r"((r)[3]) : "r"(a))
#define LDSM4T(r, a) \
    asm volatile("ldmatrix.sync.aligned.m8n8.x4.trans.shared.b16 {%0,%1,%2,%3}, [%4];" \
        : "=r"((r)[0]), "=r"((r)[1]), "=r"((r)[2]), "=r"((r)[3]) : "r"(a))
#define MMA16816(d, a, b0, b1) \
    asm volatile("mma.sync.aligned.m16n8k16.row.col.f32.f16.f16.f32 " \
        "{%0,%1,%2,%3}, {%4,%5,%6,%7}, {%8,%9}, {%0,%1,%2,%3};" \
        : "+f"((d)[0]), "+f"((d)[1]), "+f"((d)[2]), "+f"((d)[3]) \
        : "r"((a)[0]), "r"((a)[1]), "r"((a)[2]), "r"((a)[3]), "r"(b0), "r"(b1))

__device__ __forceinline__ uint32_t sptr(const void* p) {
    return (uint32_t)__cvta_generic_to_shared(p);
}

// A convert: float4 -> fp16 hi pair + fp16 residual pair.
__device__ __forceinline__ void cvt_store_a(char* hip, char* lop, float4 f) {
    __half2 h01 = __floats2half2_rn(f.x, f.y);
    __half2 h23 = __floats2half2_rn(f.z, f.w);
    float rx = f.x - __low2float(h01);
    float ry = f.y - __high2float(h01);
    float rz = f.z - __low2float(h23);
    float rw = f.w - __high2float(h23);
    __half2 l01 = __floats2half2_rn(rx, ry);
    __half2 l23 = __floats2half2_rn(rz, rw);
    *(uint2*)hip = make_uint2(*(uint32_t*)&h01, *(uint32_t*)&h23);
    *(uint2*)lop = make_uint2(*(uint32_t*)&l01, *(uint32_t*)&l23);
}
// B convert: float4 -> fp16 pair (hi only).
__device__ __forceinline__ void cvt_store_b(char* hip, float4 f) {
    __half2 h01 = __floats2half2_rn(f.x, f.y);
    __half2 h23 = __floats2half2_rn(f.z, f.w);
    *(uint2*)hip = make_uint2(*(uint32_t*)&h01, *(uint32_t*)&h23);
}

#define BKK 32
#define ASTR 40    // padded A row (32 + 8 fp16 elems)

// FFN1: D = silu(x @ w1 + b1) -> g_h ; FFN2: D = (h @ w2 + b2)*prob -> out
template<int K_TOTAL, int A_STRIDE, int B_STRIDE, bool FFN1,
         int BMT, int BNT, int NT, int MINB>
__global__ void __launch_bounds__(NT, MINB)
ffn_mma_kernel(const float* __restrict__ Asrc, const float* __restrict__ Bsrc,
               const float* __restrict__ bias, float* __restrict__ Dst) {
    constexpr int BSTR = BNT + 8;
    constexpr int ASZ  = BMT * ASTR * 2;
    constexpr int BSZ  = BKK * BSTR * 2;
    constexpr int O_AH = 0;
    constexpr int O_AL = O_AH + ASZ;
    constexpr int O_BH = O_AL + ASZ;
    constexpr int BUF_BYTES = 2 * ASZ + BSZ;
    constexpr int NWN  = BNT / 32;            // warps along N
    constexpr int TPRA = NT / BMT;            // threads per A row
    constexpr int AF4  = 32 / TPRA / 4;       // float4 per thread (A)
    constexpr int TPRB = NT / BKK;            // threads per B row
    constexpr int BF4  = BNT / TPRB / 4;      // float4 per thread (B)

    const int e = blockIdx.y;
    const int cnt = g_cnt[e];
    const int m0 = blockIdx.z * BMT;
    if (m0 >= cnt) return;
    const int n0 = blockIdx.x * BNT;

    extern __shared__ __align__(16) char dsm[];
    __shared__ int toks_s[BMT];

    const int tid = threadIdx.x;
    const int wid = tid >> 5;
    const int lane = tid & 31;
    const int warp_m = wid / NWN;
    const int warp_n = wid % NWN;

    if (tid < BMT) {
        int m = m0 + tid;
        toks_s[tid] = (m < cnt) ? g_idx[e * T_TOK + m] : -1;
    }
    __syncthreads();

    // loader mapping
    const int a_row = tid / TPRA;
    const int a_cg  = (tid % TPRA) * (32 / TPRA);
    const int tokA  = toks_s[a_row];
    const float* arow = (tokA >= 0) ? (Asrc + (size_t)tokA * A_STRIDE) : nullptr;
    const int b_row = tid / TPRB;
    const int b_cg  = (tid % TPRB) * (BNT / TPRB);
    const float* brow = Bsrc + (size_t)e * K_TOTAL * B_STRIDE
                       + (size_t)b_row * B_STRIDE + n0 + b_cg;

    const uint32_t a_sts = (uint32_t)((a_row * ASTR + a_cg) * 2);
    const uint32_t b_sts = (uint32_t)((b_row * BSTR + b_cg) * 2);

    float4 ra[AF4], rb[BF4];
    // prologue: LDG iter 0
#pragma unroll
    for (int j = 0; j < AF4; j++)
        ra[j] = arow ? *(const float4*)(arow + a_cg + j * 4)
                     : make_float4(0.f, 0.f, 0.f, 0.f);
#pragma unroll
    for (int j = 0; j < BF4; j++)
        rb[j] = *(const float4*)(brow + j * 4);
    // STS iter 0 -> buffer 0
#pragma unroll
    for (int j = 0; j < AF4; j++)
        cvt_store_a(dsm + O_AH + a_sts + j * 8, dsm + O_AL + a_sts + j * 8, ra[j]);
#pragma unroll
    for (int j = 0; j < BF4; j++)
        cvt_store_b(dsm + O_BH + b_sts + j * 8, rb[j]);
    // LDG iter 1
    if (K_TOTAL > BKK) {
#pragma unroll
        for (int j = 0; j < AF4; j++)
            ra[j] = arow ? *(const float4*)(arow + BKK + a_cg + j * 4)
                         : make_float4(0.f, 0.f, 0.f, 0.f);
#pragma unroll
        for (int j = 0; j < BF4; j++)
            rb[j] = *(const float4*)(brow + (size_t)BKK * B_STRIDE + j * 4);
    }
    __syncthreads();

    float acc[2][4][4];
#pragma unroll
    for (int mi = 0; mi < 2; mi++)
#pragma unroll
        for (int nj = 0; nj < 4; nj++)
#pragma unroll
            for (int q = 0; q < 4; q++) acc[mi][nj][q] = 0.f;

    const uint32_t dynb = sptr(dsm);
    const int lm  = lane & 15;
    const int lg8 = (lane >> 4) * 8;
    const uint32_t aoff = (uint32_t)(((warp_m * 32 + lm) * ASTR + lg8) * 2);
    const uint32_t boff = (uint32_t)((lm * BSTR + warp_n * 32 + lg8) * 2);

    const int n_iters = K_TOTAL / BKK;
    for (int it = 0; it < n_iters; ++it) {
        const int cur = it & 1;

        // STS iter it+1 into the other buffer
        if (it + 1 < n_iters) {
            char* nb = dsm + (cur ^ 1) * BUF_BYTES;
#pragma unroll
            for (int j = 0; j < AF4; j++)
                cvt_store_a(nb + O_AH + a_sts + j * 8, nb + O_AL + a_sts + j * 8, ra[j]);
#pragma unroll
            for (int j = 0; j < BF4; j++)
                cvt_store_b(nb + O_BH + b_sts + j * 8, rb[j]);
        }
        // LDG iter it+2 into registers
        if (it + 2 < n_iters) {
            const int k0 = (it + 2) * BKK;
#pragma unroll
            for (int j = 0; j < AF4; j++)
                ra[j] = arow ? *(const float4*)(arow + k0 + a_cg + j * 4)
                             : make_float4(0.f, 0.f, 0.f, 0.f);
#pragma unroll
            for (int j = 0; j < BF4; j++)
                rb[j] = *(const float4*)(brow + (size_t)k0 * B_STRIDE + j * 4);
        }

        // compute current buffer: 2 x k16 steps, 2-term fp16 split
        const uint32_t aH = dynb + cur * BUF_BYTES + O_AH;
        const uint32_t aL = dynb + cur * BUF_BYTES + O_AL;
        const uint32_t bH = dynb + cur * BUF_BYTES + O_BH;
#pragma unroll
        for (int kk = 0; kk < 2; kk++) {
            uint32_t fah[2][4], fal[2][4], fbh[2][4];
#pragma unroll
            for (int ni = 0; ni < 2; ni++) {
                uint32_t ba = boff + (uint32_t)((kk * 16 * BSTR + ni * 16) * 2);
                LDSM4T(fbh[ni], bH + ba);
            }
#pragma unroll
            for (int mi = 0; mi < 2; mi++) {
                uint32_t aa = aoff + (uint32_t)((mi * 16 * ASTR + kk * 16) * 2);
                LDSM4(fah[mi], aH + aa);
                LDSM4(fal[mi], aL + aa);
            }
#pragma unroll
            for (int mi = 0; mi < 2; mi++) {
#pragma unroll
                for (int nj = 0; nj < 4; nj++) {
                    uint32_t b0 = fbh[nj >> 1][(nj & 1) * 2];
                    uint32_t b1 = fbh[nj >> 1][(nj & 1) * 2 + 1];
                    MMA16816(acc[mi][nj], fah[mi], b0, b1);
                    MMA16816(acc[mi][nj], fal[mi], b0, b1);
                }
            }
        }
        __syncthreads();
    }

    // epilogue: straight from registers
    const int r4 = lane >> 2;
    const int c2 = (lane & 3) * 2;
    const float* bias_p = bias + (size_t)e * B_STRIDE + n0 + warp_n * 32;
#pragma unroll
    for (int mi = 0; mi < 2; mi++) {
#pragma unroll
        for (int half = 0; half < 2; half++) {
            int rl = warp_m * 32 + mi * 16 + half * 8 + r4;
            int tok = toks_s[rl];
            if (tok < 0) continue;
            float p = 1.f;
            if (!FFN1) p = g_prob[tok];
            float* drow = Dst + (size_t)tok * B_STRIDE + n0 + warp_n * 32;
#pragma unroll
            for (int nj = 0; nj < 4; nj++) {
                int c = nj * 8 + c2;
                float v0 = acc[mi][nj][half * 2 + 0] + bias_p[c];
                float v1 = acc[mi][nj][half * 2 + 1] + bias_p[c + 1];
                float2 o;
                if (FFN1) {
                    o.x = v0 / (1.f + expf(-v0));
                    o.y = v1 / (1.f + expf(-v1));
                } else {
                    o.x = v0 * p;
                    o.y = v1 * p;
                }
                *(float2*)(drow + c) = o;
            }
        }
    }
}

// ---------------------------------------------------------------------------
// Instantiation parameters
// FFN1: BM=128, BN=128, 512 threads (16 warps, 4x4)
// FFN2: BM=64,  BN=64,  128 threads (4 warps, 2x2) -> many small CTAs
#define F1_SMEM (2 * (2 * (128 * ASTR * 2) + (BKK * (128 + 8) * 2)))
#define F2_SMEM (2 * (2 * (64 * ASTR * 2) + (BKK * (64 + 8) * 2)))

extern "C" void kernel_launch(void* const* d_in, const int* in_sizes, int n_in,
                              void* d_out, int out_size) {
    const float* x  = (const float*)d_in[0];
    const float* rw = (const float*)d_in[1];
    const float* rb = (const float*)d_in[2];
    const float* w1 = (const float*)d_in[3];
    const float* b1 = (const float*)d_in[4];
    const float* w2 = (const float*)d_in[5];
    const float* b2 = (const float*)d_in[6];
    float* out = (float*)d_out;

    cudaFuncSetAttribute(
        ffn_mma_kernel<C_DIM, C_DIM, F_DIM, true, 128, 128, 512, 1>,
        cudaFuncAttributeMaxDynamicSharedMemorySize, F1_SMEM);
    cudaFuncSetAttribute(
        ffn_mma_kernel<F_DIM, F_DIM, C_DIM, false, 64, 64, 128, 2>,
        cudaFuncAttributeMaxDynamicSharedMemorySize, F2_SMEM);

    float* h = nullptr;
    cudaGetSymbolAddress((void**)&h, g_h);

    init_kernel<<<1, 32>>>();
    router_kernel<<<ROUTER_BLOCKS, 256>>>(x, rw, rb);
    aux_kernel<<<1, 256>>>(out, out_size);

    // FFN1: [cnt_e,1024] @ [1024,4096] -> silu -> g_h
    ffn_mma_kernel<C_DIM, C_DIM, F_DIM, true, 128, 128, 512, 1>
        <<<dim3(F_DIM / 128, E_NUM, T_TOK / 128), 512, F1_SMEM>>>(x, w1, b1, h);
    // FFN2: [cnt_e,4096] @ [4096,1024] -> *prob -> out (64x64 tiles for occupancy)
    ffn_mma_kernel<F_DIM, F_DIM, C_DIM, false, 64, 64, 128, 2>
        <<<dim3(C_DIM / 64, E_NUM, T_TOK / 64), 128, F2_SMEM>>>(h, w2, b2, out);
}